// round 10
// baseline (speedup 1.0000x reference)
#include <cuda_runtime.h>
#include <cuda_fp16.h>
#include <cstdint>

#define N_NODES  100000
#define N_EDGES  1600000
#define N_GRAPHS 512

// ---------------- scratch (device globals) ----------------------------------
__device__ int      g_counts[N_NODES];
__device__ int      g_rowstart[N_NODES + 1];
__device__ int      g_pos[N_NODES];
__device__ int      g_esrc[N_EDGES];
__device__ int      g_blocksums[128];
__device__ float    g_dinv[N_NODES];
__device__ uint32_t g_W1t[128 * 84];    // W1^T [n][k] tf32, k padded to 84
__device__ uint32_t g_W2t[256 * 132];   // W2^T [n][k] tf32, k padded to 132
__device__ __half2  g_xh[(size_t)N_NODES * 40];    // x in fp16, row = 40 half2 (78+2 pad)
__device__ __half2  g_h1h[(size_t)N_NODES * 64];   // h1 in fp16, row = 64 half2
__device__ float    g_pool[N_GRAPHS * 256];
__device__ float    g_mlp1[N_GRAPHS * 1024];

// ---------------- tf32 helpers ----------------------------------------------
__device__ __forceinline__ uint32_t f2tf32(float f) {
    uint32_t u;
    asm("cvt.rna.tf32.f32 %0, %1;" : "=r"(u) : "f"(f));
    return u;
}

__device__ __forceinline__ void mma_tf32(float* c, const uint32_t* a,
                                         uint32_t b0, uint32_t b1) {
    asm volatile(
        "mma.sync.aligned.m16n8k8.row.col.f32.tf32.tf32.f32 "
        "{%0,%1,%2,%3}, {%4,%5,%6,%7}, {%8,%9}, {%0,%1,%2,%3};"
        : "+f"(c[0]), "+f"(c[1]), "+f"(c[2]), "+f"(c[3])
        : "r"(a[0]), "r"(a[1]), "r"(a[2]), "r"(a[3]), "r"(b0), "r"(b1));
}

// ---------------- CSR build --------------------------------------------------
__global__ void zero_counts_kernel() {
    int i = blockIdx.x * blockDim.x + threadIdx.x;
    if (i < N_NODES) g_counts[i] = 0;
}

__global__ void hist_kernel(const int* __restrict__ ei) {
    int e = blockIdx.x * blockDim.x + threadIdx.x;
    if (e < N_EDGES) {
        int d = ei[N_EDGES + e];
        if (d >= 0 && d < N_NODES) atomicAdd(&g_counts[d], 1);
    }
}

__device__ __forceinline__ int warp_incl_scan(int x) {
    int lane = threadIdx.x & 31;
#pragma unroll
    for (int o = 1; o < 32; o <<= 1) {
        int y = __shfl_up_sync(0xffffffffu, x, o);
        if (lane >= o) x += y;
    }
    return x;
}

__global__ void scan_chunks_kernel() {
    int base = blockIdx.x * 1024;
    int t = threadIdx.x;
    int i0 = base + t * 4;
    int v[4];
#pragma unroll
    for (int j = 0; j < 4; j++) v[j] = (i0 + j < N_NODES) ? g_counts[i0 + j] : 0;
    int s = v[0] + v[1] + v[2] + v[3];
    int incl = warp_incl_scan(s);
    __shared__ int ws[8];
    int lane = t & 31, wid = t >> 5;
    if (lane == 31) ws[wid] = incl;
    __syncthreads();
    if (wid == 0) {
        int w = (lane < 8) ? ws[lane] : 0;
        w = warp_incl_scan(w);
        if (lane < 8) ws[lane] = w;
    }
    __syncthreads();
    int excl = incl - s + (wid ? ws[wid - 1] : 0);
    int run = excl;
#pragma unroll
    for (int j = 0; j < 4; j++) {
        if (i0 + j < N_NODES) g_rowstart[i0 + j] = run;
        run += v[j];
    }
    if (t == 255) g_blocksums[blockIdx.x] = excl + s;
}

__global__ void scan_tops_kernel(int nb) {
    int t = threadIdx.x;
    int v = (t < nb) ? g_blocksums[t] : 0;
    int incl = warp_incl_scan(v);
    __shared__ int ws[4];
    int lane = t & 31, wid = t >> 5;
    if (lane == 31) ws[wid] = incl;
    __syncthreads();
    if (wid == 0) {
        int w = (lane < 4) ? ws[lane] : 0;
        w = warp_incl_scan(w);
        if (lane < 4) ws[lane] = w;
    }
    __syncthreads();
    int tot_incl = incl + (wid ? ws[wid - 1] : 0);
    if (t < nb) g_blocksums[t] = tot_incl - v;
}

__global__ void scan_finalize_kernel() {
    int i = blockIdx.x * blockDim.x + threadIdx.x;
    if (i < N_NODES) {
        int v = g_rowstart[i] + g_blocksums[i >> 10];
        g_rowstart[i] = v;
        g_pos[i] = v;
        g_dinv[i] = rsqrtf((float)g_counts[i] + 1.0f);
    }
    if (i == 0) g_rowstart[N_NODES] = N_EDGES;
}

__global__ void fill_kernel(const int* __restrict__ ei) {
    int e = blockIdx.x * blockDim.x + threadIdx.x;
    if (e < N_EDGES) {
        int d = ei[N_EDGES + e];
        int s = ei[e];
        if (d >= 0 && d < N_NODES) {
            int idx = atomicAdd(&g_pos[d], 1);
            if (idx >= 0 && idx < N_EDGES) g_esrc[idx] = s;
        }
    }
}

// ---------------- prep: W1t/W2t tf32 transpose + pool zero -------------------
__global__ void prep_small_kernel(const float* __restrict__ W1,
                                  const float* __restrict__ W2) {
    int idx = blockIdx.x * blockDim.x + threadIdx.x;
    if (idx < 128 * 84) {
        int n = idx / 84, k = idx % 84;
        g_W1t[idx] = (k < 78) ? f2tf32(W1[k * 128 + n]) : 0u;
    } else if (idx < 128 * 84 + 256 * 132) {
        int j = idx - 128 * 84;
        int n = j / 132, k = j % 132;
        g_W2t[j] = (k < 128) ? f2tf32(W2[k * 256 + n]) : 0u;
    } else if (idx < 128 * 84 + 256 * 132 + N_GRAPHS * 256) {
        g_pool[idx - 128 * 84 - 256 * 132] = 0.0f;
    }
}

// x [N,78] fp32 -> g_xh [N,40] half2 (pad cols 78,79 = 0)
__global__ void xh_kernel(const float* __restrict__ x) {
    int idx = blockIdx.x * blockDim.x + threadIdx.x;
    if (idx < N_NODES * 40) {
        int row = idx / 40, q = idx % 40;
        int c = q * 2;
        float v0 = (c < 78) ? x[(size_t)row * 78 + c] : 0.0f;
        float v1 = (c + 1 < 78) ? x[(size_t)row * 78 + c + 1] : 0.0f;
        g_xh[idx] = __floats2half2_rn(v0, v1);
    }
}

// ---------------- fused layer 1: agg(xh) + TF32 GEMM + bias + relu -> h1h ----
// block = 128 nodes, 512 threads (16 warps). SMEM: As[128][84] + Bs[128][84].
// Edge loop unrolled x4 for MLP (latency-bound gather phase).
__global__ void __launch_bounds__(512)
fused1_kernel(const float* __restrict__ bias) {
    extern __shared__ uint32_t sm1[];
    uint32_t* As = sm1;                 // 128*84
    uint32_t* Bs = sm1 + 128 * 84;      // 128*84
    int tid = threadIdx.x, wid = tid >> 5, lane = tid & 31;
    int tileBase = blockIdx.x * 128;

    // stage W1t -> Bs
    for (int idx = tid; idx < 128 * 20; idx += 512) {
        int n = idx / 20, q = idx % 20;
        ((uint4*)(Bs + n * 84))[q] = ((const uint4*)(g_W1t + n * 84))[q];
    }

    // aggregation: warp per node, 8 nodes per warp, edges unrolled x4
    for (int r = 0; r < 8; r++) {
        int row = wid + r * 16;
        int i = tileBase + row;
        float a0 = 0.f, a1 = 0.f, a2 = 0.f, a3 = 0.f;
        if (i < N_NODES) {
            float di = g_dinv[i];
            int beg = g_rowstart[i], end = g_rowstart[i + 1];
            int e = beg;
            for (; e + 4 <= end; e += 4) {
                int s0 = g_esrc[e], s1 = g_esrc[e + 1];
                int s2 = g_esrc[e + 2], s3 = g_esrc[e + 3];
                float w0 = g_dinv[s0] * di, w1 = g_dinv[s1] * di;
                float w2 = g_dinv[s2] * di, w3 = g_dinv[s3] * di;
                const __half2* x0 = g_xh + (size_t)s0 * 40;
                const __half2* x1 = g_xh + (size_t)s1 * 40;
                const __half2* x2 = g_xh + (size_t)s2 * 40;
                const __half2* x3 = g_xh + (size_t)s3 * 40;
                __half2 h0 = x0[lane], h1v = x1[lane], h2v = x2[lane], h3 = x3[lane];
                float2 p0 = __half22float2(h0), p1 = __half22float2(h1v);
                float2 p2 = __half22float2(h2v), p3 = __half22float2(h3);
                a0 += p0.x * w0 + p1.x * w1 + p2.x * w2 + p3.x * w3;
                a1 += p0.y * w0 + p1.y * w1 + p2.y * w2 + p3.y * w3;
                if (lane < 8) {
                    float2 q0 = __half22float2(x0[32 + lane]);
                    float2 q1 = __half22float2(x1[32 + lane]);
                    float2 q2 = __half22float2(x2[32 + lane]);
                    float2 q3 = __half22float2(x3[32 + lane]);
                    a2 += q0.x * w0 + q1.x * w1 + q2.x * w2 + q3.x * w3;
                    a3 += q0.y * w0 + q1.y * w1 + q2.y * w2 + q3.y * w3;
                }
            }
            for (; e < end; e++) {
                int s = g_esrc[e];
                float w = g_dinv[s] * di;
                const __half2* xs = g_xh + (size_t)s * 40;
                float2 p = __half22float2(xs[lane]);
                a0 += p.x * w; a1 += p.y * w;
                if (lane < 8) {
                    float2 q = __half22float2(xs[32 + lane]);
                    a2 += q.x * w; a3 += q.y * w;
                }
            }
            float sd = di * di;
            const __half2* xi = g_xh + (size_t)i * 40;
            float2 p = __half22float2(xi[lane]);
            a0 += p.x * sd; a1 += p.y * sd;
            if (lane < 8) {
                float2 q = __half22float2(xi[32 + lane]);
                a2 += q.x * sd; a3 += q.y * sd;
            }
        }
        As[row * 84 + 2 * lane] = f2tf32(a0);
        As[row * 84 + 2 * lane + 1] = f2tf32(a1);
        if (lane < 8) {
            As[row * 84 + 64 + 2 * lane] = f2tf32(a2);
            As[row * 84 + 64 + 2 * lane + 1] = f2tf32(a3);
        }
    }
    __syncthreads();

    // MMA: 16 warps, warp tile 32 rows x 32 cols, K=80
    int lq = lane >> 2, lr = lane & 3;
    int warpRow = wid & 3, warpCol = wid >> 2;
    float c[2][4][4] = {};
#pragma unroll
    for (int ks = 0; ks < 10; ks++) {
        uint32_t a[2][4];
#pragma unroll
        for (int am = 0; am < 2; am++) {
            int rr = warpRow * 32 + am * 16 + lq;
            a[am][0] = As[rr * 84 + ks * 8 + lr];
            a[am][1] = As[(rr + 8) * 84 + ks * 8 + lr];
            a[am][2] = As[rr * 84 + ks * 8 + lr + 4];
            a[am][3] = As[(rr + 8) * 84 + ks * 8 + lr + 4];
        }
#pragma unroll
        for (int an = 0; an < 4; an++) {
            int n = warpCol * 32 + an * 8 + lq;
            uint32_t b0 = Bs[n * 84 + ks * 8 + lr];
            uint32_t b1 = Bs[n * 84 + ks * 8 + lr + 4];
            mma_tf32(c[0][an], a[0], b0, b1);
            mma_tf32(c[1][an], a[1], b0, b1);
        }
    }

    // epilogue -> h1h (bias + relu, fp16 pair stores)
#pragma unroll
    for (int am = 0; am < 2; am++) {
        int r0 = tileBase + warpRow * 32 + am * 16 + lq;
#pragma unroll
        for (int an = 0; an < 4; an++) {
            int col = warpCol * 32 + an * 8 + lr * 2;
            float bx = bias[col], by = bias[col + 1];
            float v0 = fmaxf(c[am][an][0] + bx, 0.f);
            float v1 = fmaxf(c[am][an][1] + by, 0.f);
            float v2 = fmaxf(c[am][an][2] + bx, 0.f);
            float v3 = fmaxf(c[am][an][3] + by, 0.f);
            if (r0 < N_NODES)
                g_h1h[(size_t)r0 * 64 + (col >> 1)] = __floats2half2_rn(v0, v1);
            if (r0 + 8 < N_NODES)
                g_h1h[(size_t)(r0 + 8) * 64 + (col >> 1)] = __floats2half2_rn(v2, v3);
        }
    }
}

// ---------------- fused layer 2: agg(h1h) + TF32 GEMM + relu + seg-max -------
// block = 128 nodes, 512 threads. SMEM: As[128][132] + Bs[256][36].
// Edge loop unrolled x4 for MLP.
__global__ void __launch_bounds__(512)
fused2_kernel(const float* __restrict__ bias, const int* __restrict__ batch) {
    extern __shared__ uint32_t sm2[];
    uint32_t* As = sm2;                  // 128*132
    uint32_t* Bs = sm2 + 128 * 132;      // 256*36
    int tid = threadIdx.x, wid = tid >> 5, lane = tid & 31;
    int tileBase = blockIdx.x * 128;

    // aggregation: warp per node over h1h [N,64 half2]
    for (int r = 0; r < 8; r++) {
        int row = wid + r * 16;
        int i = tileBase + row;
        float4 acc = make_float4(0.f, 0.f, 0.f, 0.f);
        if (i < N_NODES) {
            float di = g_dinv[i];
            int beg = g_rowstart[i], end = g_rowstart[i + 1];
            int e = beg;
            for (; e + 4 <= end; e += 4) {
                int s0 = g_esrc[e], s1 = g_esrc[e + 1];
                int s2 = g_esrc[e + 2], s3 = g_esrc[e + 3];
                float w0 = g_dinv[s0] * di, w1 = g_dinv[s1] * di;
                float w2 = g_dinv[s2] * di, w3 = g_dinv[s3] * di;
                uint2 u0 = ((const uint2*)(g_h1h + (size_t)s0 * 64))[lane];
                uint2 u1 = ((const uint2*)(g_h1h + (size_t)s1 * 64))[lane];
                uint2 u2 = ((const uint2*)(g_h1h + (size_t)s2 * 64))[lane];
                uint2 u3 = ((const uint2*)(g_h1h + (size_t)s3 * 64))[lane];
                float2 a0 = __half22float2(*(__half2*)&u0.x);
                float2 b0 = __half22float2(*(__half2*)&u0.y);
                float2 a1 = __half22float2(*(__half2*)&u1.x);
                float2 b1 = __half22float2(*(__half2*)&u1.y);
                float2 a2 = __half22float2(*(__half2*)&u2.x);
                float2 b2 = __half22float2(*(__half2*)&u2.y);
                float2 a3 = __half22float2(*(__half2*)&u3.x);
                float2 b3 = __half22float2(*(__half2*)&u3.y);
                acc.x += a0.x * w0 + a1.x * w1 + a2.x * w2 + a3.x * w3;
                acc.y += a0.y * w0 + a1.y * w1 + a2.y * w2 + a3.y * w3;
                acc.z += b0.x * w0 + b1.x * w1 + b2.x * w2 + b3.x * w3;
                acc.w += b0.y * w0 + b1.y * w1 + b2.y * w2 + b3.y * w3;
            }
            for (; e < end; e++) {
                int s = g_esrc[e];
                float w = g_dinv[s] * di;
                uint2 u = ((const uint2*)(g_h1h + (size_t)s * 64))[lane];
                float2 pa = __half22float2(*(__half2*)&u.x);
                float2 pb = __half22float2(*(__half2*)&u.y);
                acc.x += pa.x * w; acc.y += pa.y * w;
                acc.z += pb.x * w; acc.w += pb.y * w;
            }
            float sd = di * di;
            uint2 u = ((const uint2*)(g_h1h + (size_t)i * 64))[lane];
            float2 pa = __half22float2(*(__half2*)&u.x);
            float2 pb = __half22float2(*(__half2*)&u.y);
            acc.x += pa.x * sd; acc.y += pa.y * sd;
            acc.z += pb.x * sd; acc.w += pb.y * sd;
        }
        ((uint4*)(As + row * 132))[lane] =
            make_uint4(f2tf32(acc.x), f2tf32(acc.y), f2tf32(acc.z), f2tf32(acc.w));
    }
    __syncthreads();

    // MMA: 16 warps, warp tile 32 rows x 64 cols; K chunked by 32
    int lq = lane >> 2, lr = lane & 3;
    int warpRow = wid & 3, warpCol = wid >> 2;
    float c[2][8][4] = {};
    for (int kc = 0; kc < 128; kc += 32) {
        for (int idx = tid; idx < 2048; idx += 512) {
            int n = idx / 8, q = idx % 8;
            ((uint4*)(Bs + n * 36))[q] = ((const uint4*)(g_W2t + n * 132 + kc))[q];
        }
        __syncthreads();
#pragma unroll
        for (int ks = 0; ks < 4; ks++) {
            uint32_t a[2][4];
#pragma unroll
            for (int am = 0; am < 2; am++) {
                int rr = warpRow * 32 + am * 16 + lq;
                a[am][0] = As[rr * 132 + kc + ks * 8 + lr];
                a[am][1] = As[(rr + 8) * 132 + kc + ks * 8 + lr];
                a[am][2] = As[rr * 132 + kc + ks * 8 + lr + 4];
                a[am][3] = As[(rr + 8) * 132 + kc + ks * 8 + lr + 4];
            }
#pragma unroll
            for (int an = 0; an < 8; an++) {
                int n = warpCol * 64 + an * 8 + lq;
                uint32_t b0 = Bs[n * 36 + ks * 8 + lr];
                uint32_t b1 = Bs[n * 36 + ks * 8 + lr + 4];
                mma_tf32(c[0][an], a[0], b0, b1);
                mma_tf32(c[1][an], a[1], b0, b1);
            }
        }
        __syncthreads();
    }

    // epilogue: bias + relu, segment max straight into pool (h2 never stored)
#pragma unroll
    for (int am = 0; am < 2; am++) {
        int r0 = tileBase + warpRow * 32 + am * 16 + lq;
        int r1 = r0 + 8;
        int b_lo = (r0 < N_NODES) ? batch[r0] : -1;
        int b_hi = (r1 < N_NODES) ? batch[r1] : -1;
        if (b_lo >= N_GRAPHS) b_lo = -1;
        if (b_hi >= N_GRAPHS) b_hi = -1;
#pragma unroll
        for (int an = 0; an < 8; an++) {
            int col = warpCol * 64 + an * 8 + lr * 2;
            float bx = bias[col], by = bias[col + 1];
            float v0 = fmaxf(c[am][an][0] + bx, 0.f);
            float v1 = fmaxf(c[am][an][1] + by, 0.f);
            float v2 = fmaxf(c[am][an][2] + bx, 0.f);
            float v3 = fmaxf(c[am][an][3] + by, 0.f);
            if (b_lo == b_hi && b_lo >= 0) {
                atomicMax((int*)&g_pool[(size_t)b_lo * 256 + col],
                          __float_as_int(fmaxf(v0, v2)));
                atomicMax((int*)&g_pool[(size_t)b_lo * 256 + col + 1],
                          __float_as_int(fmaxf(v1, v3)));
            } else {
                if (b_lo >= 0) {
                    atomicMax((int*)&g_pool[(size_t)b_lo * 256 + col], __float_as_int(v0));
                    atomicMax((int*)&g_pool[(size_t)b_lo * 256 + col + 1], __float_as_int(v1));
                }
                if (b_hi >= 0) {
                    atomicMax((int*)&g_pool[(size_t)b_hi * 256 + col], __float_as_int(v2));
                    atomicMax((int*)&g_pool[(size_t)b_hi * 256 + col + 1], __float_as_int(v3));
                }
            }
        }
    }
}

// ---------------- fp32 MLP head (small) -------------------------------------
__global__ void __launch_bounds__(256)
mlp1_kernel(const float* __restrict__ Wg1, const float* __restrict__ bias) {
    constexpr int BM = 64, BN = 128, KC = 16, TM = 8, TN = 4, NT = 256;
    __shared__ __align__(16) float As[KC][BM];
    __shared__ __align__(16) float Bs[KC][BN];
    const float* A = g_pool; const float* B = Wg1; float* C = g_mlp1;
    const int lda = 256, ldb = 1024, ldc = 1024, nrows = N_GRAPHS, K = 256;
    int tid = threadIdx.x;
    int tx = tid % (BN / TN), ty = tid / (BN / TN);
    int rowBase = blockIdx.y * BM, colBase = blockIdx.x * BN;
    float acc[TM][TN];
#pragma unroll
    for (int i = 0; i < TM; i++)
#pragma unroll
        for (int j = 0; j < TN; j++) acc[i][j] = 0.0f;
    for (int kc = 0; kc < K; kc += KC) {
#pragma unroll
        for (int e = tid * 4; e < BM * KC; e += NT * 4) {
            int r = e / KC, k = e % KC;
            int row = rowBase + r;
            float4 v = (row < nrows) ? *(const float4*)&A[(size_t)row * lda + kc + k]
                                     : make_float4(0.f, 0.f, 0.f, 0.f);
            As[k][r] = v.x; As[k + 1][r] = v.y; As[k + 2][r] = v.z; As[k + 3][r] = v.w;
        }
#pragma unroll
        for (int e = tid * 4; e < KC * BN; e += NT * 4) {
            int k = e / BN, c = e % BN;
            *(float4*)&Bs[k][c] = *(const float4*)&B[(size_t)(kc + k) * ldb + colBase + c];
        }
        __syncthreads();
#pragma unroll
        for (int k = 0; k < KC; k++) {
            float a[TM], b[TN];
#pragma unroll
            for (int i = 0; i < TM; i++) a[i] = As[k][ty * TM + i];
#pragma unroll
            for (int j = 0; j < TN; j++) b[j] = Bs[k][tx * TN + j];
#pragma unroll
            for (int i = 0; i < TM; i++)
#pragma unroll
                for (int j = 0; j < TN; j++) acc[i][j] += a[i] * b[j];
        }
        __syncthreads();
    }
#pragma unroll
    for (int i = 0; i < TM; i++) {
        int row = rowBase + ty * TM + i;
        if (row >= nrows) continue;
#pragma unroll
        for (int j = 0; j < TN; j++) {
            int col = colBase + tx * TN + j;
            C[(size_t)row * ldc + col] = fmaxf(acc[i][j] + bias[col], 0.0f);
        }
    }
}

__global__ void __launch_bounds__(256)
mlp2_kernel(const float* __restrict__ Wg2, const float* __restrict__ bias,
            float* __restrict__ out) {
    constexpr int BM = 8, BN = 128, KC = 16, TM = 1, TN = 4, NT = 256;
    __shared__ __align__(16) float As[KC][BM];
    __shared__ __align__(16) float Bs[KC][BN];
    const float* A = g_mlp1; const float* B = Wg2; float* C = out;
    const int lda = 1024, ldb = 128, ldc = 128, nrows = N_GRAPHS, K = 1024;
    int tid = threadIdx.x;
    int tx = tid % (BN / TN), ty = tid / (BN / TN);
    int rowBase = blockIdx.y * BM, colBase = blockIdx.x * BN;
    float acc[TM][TN];
#pragma unroll
    for (int i = 0; i < TM; i++)
#pragma unroll
        for (int j = 0; j < TN; j++) acc[i][j] = 0.0f;
    for (int kc = 0; kc < K; kc += KC) {
        for (int e = tid; e < BM * KC; e += NT) {
            int r = e / KC, k = e % KC;
            int row = rowBase + r;
            As[k][r] = (row < nrows) ? A[(size_t)row * lda + kc + k] : 0.0f;
        }
#pragma unroll
        for (int e = tid * 4; e < KC * BN; e += NT * 4) {
            int k = e / BN, c = e % BN;
            *(float4*)&Bs[k][c] = *(const float4*)&B[(size_t)(kc + k) * ldb + colBase + c];
        }
        __syncthreads();
#pragma unroll
        for (int k = 0; k < KC; k++) {
            float a[TM], b[TN];
#pragma unroll
            for (int i = 0; i < TM; i++) a[i] = As[k][ty * TM + i];
#pragma unroll
            for (int j = 0; j < TN; j++) b[j] = Bs[k][tx * TN + j];
#pragma unroll
            for (int i = 0; i < TM; i++)
#pragma unroll
                for (int j = 0; j < TN; j++) acc[i][j] += a[i] * b[j];
        }
        __syncthreads();
    }
#pragma unroll
    for (int i = 0; i < TM; i++) {
        int row = rowBase + ty * TM + i;
        if (row >= nrows) continue;
#pragma unroll
        for (int j = 0; j < TN; j++) {
            int col = colBase + tx * TN + j;
            C[(size_t)row * ldc + col] = acc[i][j] + bias[col];
        }
    }
}

// ---------------- host ------------------------------------------------------
extern "C" void kernel_launch(void* const* d_in, const int* in_sizes, int n_in,
                              void* d_out, int out_size) {
    const float* x     = (const float*)d_in[0];
    const int*   ei    = (const int*)d_in[1];    // int32 (JAX x64 disabled)
    const int*   batch = (const int*)d_in[2];    // int32
    const float* W1    = (const float*)d_in[3];
    const float* b1    = (const float*)d_in[4];
    const float* W2    = (const float*)d_in[5];
    const float* b2    = (const float*)d_in[6];
    const float* Wg1   = (const float*)d_in[7];
    const float* bg1   = (const float*)d_in[8];
    const float* Wg2   = (const float*)d_in[9];
    const float* bg2   = (const float*)d_in[10];
    float*       out   = (float*)d_out;

    const int SMEM1 = 128 * 84 * 2 * 4;               // 86016 B
    const int SMEM2 = (128 * 132 + 256 * 36) * 4;     // 104448 B
    cudaFuncSetAttribute(fused1_kernel, cudaFuncAttributeMaxDynamicSharedMemorySize, SMEM1);
    cudaFuncSetAttribute(fused2_kernel, cudaFuncAttributeMaxDynamicSharedMemorySize, SMEM2);

    const int NB_SCAN = (N_NODES + 1023) / 1024;  // 98
    const int NB_ROWS = (N_NODES + 127) / 128;    // 782
    const int PREP_N  = 128 * 84 + 256 * 132 + N_GRAPHS * 256;

    // CSR build + prep
    zero_counts_kernel<<<(N_NODES + 255) / 256, 256>>>();
    hist_kernel<<<(N_EDGES + 255) / 256, 256>>>(ei);
    scan_chunks_kernel<<<NB_SCAN, 256>>>();
    scan_tops_kernel<<<1, 128>>>(NB_SCAN);
    scan_finalize_kernel<<<(N_NODES + 255) / 256, 256>>>();
    fill_kernel<<<(N_EDGES + 255) / 256, 256>>>(ei);
    prep_small_kernel<<<(PREP_N + 255) / 256, 256>>>(W1, W2);
    xh_kernel<<<(N_NODES * 40 + 255) / 256, 256>>>(x);

    // fused layers
    fused1_kernel<<<NB_ROWS, 512, SMEM1>>>(b1);
    fused2_kernel<<<NB_ROWS, 512, SMEM2>>>(b2, batch);

    // MLP head
    mlp1_kernel<<<dim3(8, 8), 256>>>(Wg1, bg1);
    mlp2_kernel<<<dim3(1, 64), 256>>>(Wg2, bg2, out);
}

// round 11
// speedup vs baseline: 1.1479x; 1.1479x over previous
#include <cuda_runtime.h>
#include <cuda_fp16.h>
#include <cstdint>

#define N_NODES  100000
#define N_EDGES  1600000
#define N_GRAPHS 512

// ---------------- scratch (device globals) ----------------------------------
__device__ int      g_counts[N_NODES];
__device__ int      g_rowstart[N_NODES + 1];
__device__ int      g_pos[N_NODES];
__device__ int      g_esrc[N_EDGES];
__device__ int      g_blocksums[128];
__device__ float    g_dinv[N_NODES];
__device__ uint32_t g_W1t[128 * 84];    // W1^T [n][k] tf32, k padded to 84
__device__ uint32_t g_W2t[256 * 132];   // W2^T [n][k] tf32, k padded to 132
__device__ __half2  g_xh[(size_t)N_NODES * 40];     // x fp16, 40 half2/row (78+2 pad)
__device__ __half2  g_aggXh[(size_t)N_NODES * 40];  // aggregated x, fp16
__device__ __half2  g_h1h[(size_t)N_NODES * 64];    // h1 fp16, 64 half2/row
__device__ __half2  g_aggHh[(size_t)N_NODES * 64];  // aggregated h1, fp16
__device__ float    g_pool[N_GRAPHS * 256];
__device__ float    g_mlp1[N_GRAPHS * 1024];

// ---------------- tf32 helpers ----------------------------------------------
__device__ __forceinline__ uint32_t f2tf32(float f) {
    uint32_t u;
    asm("cvt.rna.tf32.f32 %0, %1;" : "=r"(u) : "f"(f));
    return u;
}

__device__ __forceinline__ void mma_tf32(float* c, const uint32_t* a,
                                         uint32_t b0, uint32_t b1) {
    asm volatile(
        "mma.sync.aligned.m16n8k8.row.col.f32.tf32.tf32.f32 "
        "{%0,%1,%2,%3}, {%4,%5,%6,%7}, {%8,%9}, {%0,%1,%2,%3};"
        : "+f"(c[0]), "+f"(c[1]), "+f"(c[2]), "+f"(c[3])
        : "r"(a[0]), "r"(a[1]), "r"(a[2]), "r"(a[3]), "r"(b0), "r"(b1));
}

// ---------------- CSR build --------------------------------------------------
__global__ void zero_counts_kernel() {
    int i = blockIdx.x * blockDim.x + threadIdx.x;
    if (i < N_NODES) g_counts[i] = 0;
}

__global__ void hist_kernel(const int* __restrict__ ei) {
    int e = blockIdx.x * blockDim.x + threadIdx.x;
    if (e < N_EDGES) {
        int d = ei[N_EDGES + e];
        if (d >= 0 && d < N_NODES) atomicAdd(&g_counts[d], 1);
    }
}

__device__ __forceinline__ int warp_incl_scan(int x) {
    int lane = threadIdx.x & 31;
#pragma unroll
    for (int o = 1; o < 32; o <<= 1) {
        int y = __shfl_up_sync(0xffffffffu, x, o);
        if (lane >= o) x += y;
    }
    return x;
}

__global__ void scan_chunks_kernel() {
    int base = blockIdx.x * 1024;
    int t = threadIdx.x;
    int i0 = base + t * 4;
    int v[4];
#pragma unroll
    for (int j = 0; j < 4; j++) v[j] = (i0 + j < N_NODES) ? g_counts[i0 + j] : 0;
    int s = v[0] + v[1] + v[2] + v[3];
    int incl = warp_incl_scan(s);
    __shared__ int ws[8];
    int lane = t & 31, wid = t >> 5;
    if (lane == 31) ws[wid] = incl;
    __syncthreads();
    if (wid == 0) {
        int w = (lane < 8) ? ws[lane] : 0;
        w = warp_incl_scan(w);
        if (lane < 8) ws[lane] = w;
    }
    __syncthreads();
    int excl = incl - s + (wid ? ws[wid - 1] : 0);
    int run = excl;
#pragma unroll
    for (int j = 0; j < 4; j++) {
        if (i0 + j < N_NODES) g_rowstart[i0 + j] = run;
        run += v[j];
    }
    if (t == 255) g_blocksums[blockIdx.x] = excl + s;
}

__global__ void scan_tops_kernel(int nb) {
    int t = threadIdx.x;
    int v = (t < nb) ? g_blocksums[t] : 0;
    int incl = warp_incl_scan(v);
    __shared__ int ws[4];
    int lane = t & 31, wid = t >> 5;
    if (lane == 31) ws[wid] = incl;
    __syncthreads();
    if (wid == 0) {
        int w = (lane < 4) ? ws[lane] : 0;
        w = warp_incl_scan(w);
        if (lane < 4) ws[lane] = w;
    }
    __syncthreads();
    int tot_incl = incl + (wid ? ws[wid - 1] : 0);
    if (t < nb) g_blocksums[t] = tot_incl - v;
}

__global__ void scan_finalize_kernel() {
    int i = blockIdx.x * blockDim.x + threadIdx.x;
    if (i < N_NODES) {
        int v = g_rowstart[i] + g_blocksums[i >> 10];
        g_rowstart[i] = v;
        g_pos[i] = v;
        g_dinv[i] = rsqrtf((float)g_counts[i] + 1.0f);
    }
    if (i == 0) g_rowstart[N_NODES] = N_EDGES;
}

__global__ void fill_kernel(const int* __restrict__ ei) {
    int e = blockIdx.x * blockDim.x + threadIdx.x;
    if (e < N_EDGES) {
        int d = ei[N_EDGES + e];
        int s = ei[e];
        if (d >= 0 && d < N_NODES) {
            int idx = atomicAdd(&g_pos[d], 1);
            if (idx >= 0 && idx < N_EDGES) g_esrc[idx] = s;
        }
    }
}

// ---------------- prep: W1t/W2t tf32 transpose + pool zero -------------------
__global__ void prep_small_kernel(const float* __restrict__ W1,
                                  const float* __restrict__ W2) {
    int idx = blockIdx.x * blockDim.x + threadIdx.x;
    if (idx < 128 * 84) {
        int n = idx / 84, k = idx % 84;
        g_W1t[idx] = (k < 78) ? f2tf32(W1[k * 128 + n]) : 0u;
    } else if (idx < 128 * 84 + 256 * 132) {
        int j = idx - 128 * 84;
        int n = j / 132, k = j % 132;
        g_W2t[j] = (k < 128) ? f2tf32(W2[k * 256 + n]) : 0u;
    } else if (idx < 128 * 84 + 256 * 132 + N_GRAPHS * 256) {
        g_pool[idx - 128 * 84 - 256 * 132] = 0.0f;
    }
}

// x [N,78] fp32 -> g_xh [N,40] half2 (pad cols 78,79 = 0)
__global__ void xh_kernel(const float* __restrict__ x) {
    int idx = blockIdx.x * blockDim.x + threadIdx.x;
    if (idx < N_NODES * 40) {
        int row = idx / 40, q = idx % 40;
        int c = q * 2;
        float v0 = (c < 78) ? x[(size_t)row * 78 + c] : 0.0f;
        float v1 = (c + 1 < 78) ? x[(size_t)row * 78 + c + 1] : 0.0f;
        g_xh[idx] = __floats2half2_rn(v0, v1);
    }
}

// ---------------- agg1: aggregate xh -> aggXh (high occupancy, no smem) ------
// warp per node; simple loop (ptxas pipelines independent iterations).
__global__ void __launch_bounds__(256)
agg1_kernel() {
    int warp = (blockIdx.x * blockDim.x + threadIdx.x) >> 5;
    int lane = threadIdx.x & 31;
    if (warp >= N_NODES) return;
    int i = warp;
    float di = g_dinv[i];
    int beg = g_rowstart[i], end = g_rowstart[i + 1];
    float a0 = 0.f, a1 = 0.f, a2 = 0.f, a3 = 0.f;
    for (int e = beg; e < end; e++) {
        int s = g_esrc[e];
        float w = g_dinv[s] * di;
        const __half2* xs = g_xh + (size_t)s * 40;
        float2 p = __half22float2(xs[lane]);
        a0 += p.x * w; a1 += p.y * w;
        if (lane < 8) {
            float2 q = __half22float2(xs[32 + lane]);
            a2 += q.x * w; a3 += q.y * w;
        }
    }
    float sd = di * di;
    const __half2* xi = g_xh + (size_t)i * 40;
    float2 p = __half22float2(xi[lane]);
    a0 += p.x * sd; a1 += p.y * sd;
    if (lane < 8) {
        float2 q = __half22float2(xi[32 + lane]);
        a2 += q.x * sd; a3 += q.y * sd;
    }
    g_aggXh[(size_t)i * 40 + lane] = __floats2half2_rn(a0, a1);
    if (lane < 8)
        g_aggXh[(size_t)i * 40 + 32 + lane] = __floats2half2_rn(a2, a3);
}

// ---------------- agg2: aggregate h1h -> aggHh (high occupancy, no smem) -----
__global__ void __launch_bounds__(256)
agg2_kernel() {
    int warp = (blockIdx.x * blockDim.x + threadIdx.x) >> 5;
    int lane = threadIdx.x & 31;
    if (warp >= N_NODES) return;
    int i = warp;
    float di = g_dinv[i];
    int beg = g_rowstart[i], end = g_rowstart[i + 1];
    float4 acc = make_float4(0.f, 0.f, 0.f, 0.f);
    for (int e = beg; e < end; e++) {
        int s = g_esrc[e];
        float w = g_dinv[s] * di;
        uint2 u = ((const uint2*)(g_h1h + (size_t)s * 64))[lane];
        float2 pa = __half22float2(*(__half2*)&u.x);
        float2 pb = __half22float2(*(__half2*)&u.y);
        acc.x += pa.x * w; acc.y += pa.y * w;
        acc.z += pb.x * w; acc.w += pb.y * w;
    }
    float sd = di * di;
    uint2 u = ((const uint2*)(g_h1h + (size_t)i * 64))[lane];
    float2 pa = __half22float2(*(__half2*)&u.x);
    float2 pb = __half22float2(*(__half2*)&u.y);
    acc.x += pa.x * sd; acc.y += pa.y * sd;
    acc.z += pb.x * sd; acc.w += pb.y * sd;
    __half2 h0 = __floats2half2_rn(acc.x, acc.y);
    __half2 h1 = __floats2half2_rn(acc.z, acc.w);
    uint2 o;
    o.x = *(uint32_t*)&h0;
    o.y = *(uint32_t*)&h1;
    ((uint2*)(g_aggHh + (size_t)i * 64))[lane] = o;
}

// ---------------- gemm1: aggXh @ W1 -> h1h (TF32 MMA, bias+relu) -------------
// block = 128 rows, 512 threads. SMEM: As[128][84] + Bs[128][84] u32.
__global__ void __launch_bounds__(512)
gemm1_kernel(const float* __restrict__ bias) {
    extern __shared__ uint32_t sm1[];
    uint32_t* As = sm1;
    uint32_t* Bs = sm1 + 128 * 84;
    int tid = threadIdx.x, wid = tid >> 5, lane = tid & 31;
    int tileBase = blockIdx.x * 128;

    // stage W1t -> Bs
    for (int idx = tid; idx < 128 * 20; idx += 512) {
        int n = idx / 20, q = idx % 20;
        ((uint4*)(Bs + n * 84))[q] = ((const uint4*)(g_W1t + n * 84))[q];
    }
    // stage aggXh -> As (fp16 -> tf32)
    for (int idx = tid; idx < 128 * 40; idx += 512) {
        int row = idx / 40, q = idx % 40;
        int gi = tileBase + row;
        float2 p = make_float2(0.f, 0.f);
        if (gi < N_NODES) p = __half22float2(g_aggXh[(size_t)gi * 40 + q]);
        As[row * 84 + 2 * q] = f2tf32(p.x);
        As[row * 84 + 2 * q + 1] = f2tf32(p.y);
    }
    __syncthreads();

    // MMA: 16 warps, warp tile 32 rows x 32 cols, K=80
    int lq = lane >> 2, lr = lane & 3;
    int warpRow = wid & 3, warpCol = wid >> 2;
    float c[2][4][4] = {};
#pragma unroll
    for (int ks = 0; ks < 10; ks++) {
        uint32_t a[2][4];
#pragma unroll
        for (int am = 0; am < 2; am++) {
            int rr = warpRow * 32 + am * 16 + lq;
            a[am][0] = As[rr * 84 + ks * 8 + lr];
            a[am][1] = As[(rr + 8) * 84 + ks * 8 + lr];
            a[am][2] = As[rr * 84 + ks * 8 + lr + 4];
            a[am][3] = As[(rr + 8) * 84 + ks * 8 + lr + 4];
        }
#pragma unroll
        for (int an = 0; an < 4; an++) {
            int n = warpCol * 32 + an * 8 + lq;
            uint32_t b0 = Bs[n * 84 + ks * 8 + lr];
            uint32_t b1 = Bs[n * 84 + ks * 8 + lr + 4];
            mma_tf32(c[0][an], a[0], b0, b1);
            mma_tf32(c[1][an], a[1], b0, b1);
        }
    }

    // epilogue -> h1h (bias + relu, fp16 pair stores)
#pragma unroll
    for (int am = 0; am < 2; am++) {
        int r0 = tileBase + warpRow * 32 + am * 16 + lq;
#pragma unroll
        for (int an = 0; an < 4; an++) {
            int col = warpCol * 32 + an * 8 + lr * 2;
            float bx = bias[col], by = bias[col + 1];
            float v0 = fmaxf(c[am][an][0] + bx, 0.f);
            float v1 = fmaxf(c[am][an][1] + by, 0.f);
            float v2 = fmaxf(c[am][an][2] + bx, 0.f);
            float v3 = fmaxf(c[am][an][3] + by, 0.f);
            if (r0 < N_NODES)
                g_h1h[(size_t)r0 * 64 + (col >> 1)] = __floats2half2_rn(v0, v1);
            if (r0 + 8 < N_NODES)
                g_h1h[(size_t)(r0 + 8) * 64 + (col >> 1)] = __floats2half2_rn(v2, v3);
        }
    }
}

// ---------------- gemm2: aggHh @ W2 -> relu -> seg-max into pool -------------
// block = 128 rows, 512 threads. SMEM: As[128][132] + Bs[256][36] u32.
__global__ void __launch_bounds__(512)
gemm2_kernel(const float* __restrict__ bias, const int* __restrict__ batch) {
    extern __shared__ uint32_t sm2[];
    uint32_t* As = sm2;
    uint32_t* Bs = sm2 + 128 * 132;
    int tid = threadIdx.x, wid = tid >> 5, lane = tid & 31;
    int tileBase = blockIdx.x * 128;

    // stage aggHh -> As (fp16 -> tf32): 128 rows x 32 uint2
    for (int idx = tid; idx < 128 * 32; idx += 512) {
        int row = idx >> 5, m = idx & 31;
        int gi = tileBase + row;
        uint2 u = make_uint2(0u, 0u);
        if (gi < N_NODES) u = ((const uint2*)(g_aggHh + (size_t)gi * 64))[m];
        float2 pa = __half22float2(*(__half2*)&u.x);
        float2 pb = __half22float2(*(__half2*)&u.y);
        uint32_t* dst = &As[row * 132 + 4 * m];
        dst[0] = f2tf32(pa.x); dst[1] = f2tf32(pa.y);
        dst[2] = f2tf32(pb.x); dst[3] = f2tf32(pb.y);
    }
    __syncthreads();

    // MMA: 16 warps, warp tile 32 rows x 64 cols; K chunked by 32
    int lq = lane >> 2, lr = lane & 3;
    int warpRow = wid & 3, warpCol = wid >> 2;
    float c[2][8][4] = {};
    for (int kc = 0; kc < 128; kc += 32) {
        for (int idx = tid; idx < 2048; idx += 512) {
            int n = idx / 8, q = idx % 8;
            ((uint4*)(Bs + n * 36))[q] = ((const uint4*)(g_W2t + n * 132 + kc))[q];
        }
        __syncthreads();
#pragma unroll
        for (int ks = 0; ks < 4; ks++) {
            uint32_t a[2][4];
#pragma unroll
            for (int am = 0; am < 2; am++) {
                int rr = warpRow * 32 + am * 16 + lq;
                a[am][0] = As[rr * 132 + kc + ks * 8 + lr];
                a[am][1] = As[(rr + 8) * 132 + kc + ks * 8 + lr];
                a[am][2] = As[rr * 132 + kc + ks * 8 + lr + 4];
                a[am][3] = As[(rr + 8) * 132 + kc + ks * 8 + lr + 4];
            }
#pragma unroll
            for (int an = 0; an < 8; an++) {
                int n = warpCol * 64 + an * 8 + lq;
                uint32_t b0 = Bs[n * 36 + ks * 8 + lr];
                uint32_t b1 = Bs[n * 36 + ks * 8 + lr + 4];
                mma_tf32(c[0][an], a[0], b0, b1);
                mma_tf32(c[1][an], a[1], b0, b1);
            }
        }
        __syncthreads();
    }

    // epilogue: bias + relu, segment max straight into pool (h2 never stored)
#pragma unroll
    for (int am = 0; am < 2; am++) {
        int r0 = tileBase + warpRow * 32 + am * 16 + lq;
        int r1 = r0 + 8;
        int b_lo = (r0 < N_NODES) ? batch[r0] : -1;
        int b_hi = (r1 < N_NODES) ? batch[r1] : -1;
        if (b_lo >= N_GRAPHS) b_lo = -1;
        if (b_hi >= N_GRAPHS) b_hi = -1;
#pragma unroll
        for (int an = 0; an < 8; an++) {
            int col = warpCol * 64 + an * 8 + lr * 2;
            float bx = bias[col], by = bias[col + 1];
            float v0 = fmaxf(c[am][an][0] + bx, 0.f);
            float v1 = fmaxf(c[am][an][1] + by, 0.f);
            float v2 = fmaxf(c[am][an][2] + bx, 0.f);
            float v3 = fmaxf(c[am][an][3] + by, 0.f);
            if (b_lo == b_hi && b_lo >= 0) {
                atomicMax((int*)&g_pool[(size_t)b_lo * 256 + col],
                          __float_as_int(fmaxf(v0, v2)));
                atomicMax((int*)&g_pool[(size_t)b_lo * 256 + col + 1],
                          __float_as_int(fmaxf(v1, v3)));
            } else {
                if (b_lo >= 0) {
                    atomicMax((int*)&g_pool[(size_t)b_lo * 256 + col], __float_as_int(v0));
                    atomicMax((int*)&g_pool[(size_t)b_lo * 256 + col + 1], __float_as_int(v1));
                }
                if (b_hi >= 0) {
                    atomicMax((int*)&g_pool[(size_t)b_hi * 256 + col], __float_as_int(v2));
                    atomicMax((int*)&g_pool[(size_t)b_hi * 256 + col + 1], __float_as_int(v3));
                }
            }
        }
    }
}

// ---------------- fp32 MLP head (small) -------------------------------------
__global__ void __launch_bounds__(256)
mlp1_kernel(const float* __restrict__ Wg1, const float* __restrict__ bias) {
    constexpr int BM = 64, BN = 128, KC = 16, TM = 8, TN = 4, NT = 256;
    __shared__ __align__(16) float As[KC][BM];
    __shared__ __align__(16) float Bs[KC][BN];
    const float* A = g_pool; const float* B = Wg1; float* C = g_mlp1;
    const int lda = 256, ldb = 1024, ldc = 1024, nrows = N_GRAPHS, K = 256;
    int tid = threadIdx.x;
    int tx = tid % (BN / TN), ty = tid / (BN / TN);
    int rowBase = blockIdx.y * BM, colBase = blockIdx.x * BN;
    float acc[TM][TN];
#pragma unroll
    for (int i = 0; i < TM; i++)
#pragma unroll
        for (int j = 0; j < TN; j++) acc[i][j] = 0.0f;
    for (int kc = 0; kc < K; kc += KC) {
#pragma unroll
        for (int e = tid * 4; e < BM * KC; e += NT * 4) {
            int r = e / KC, k = e % KC;
            int row = rowBase + r;
            float4 v = (row < nrows) ? *(const float4*)&A[(size_t)row * lda + kc + k]
                                     : make_float4(0.f, 0.f, 0.f, 0.f);
            As[k][r] = v.x; As[k + 1][r] = v.y; As[k + 2][r] = v.z; As[k + 3][r] = v.w;
        }
#pragma unroll
        for (int e = tid * 4; e < KC * BN; e += NT * 4) {
            int k = e / BN, c = e % BN;
            *(float4*)&Bs[k][c] = *(const float4*)&B[(size_t)(kc + k) * ldb + colBase + c];
        }
        __syncthreads();
#pragma unroll
        for (int k = 0; k < KC; k++) {
            float a[TM], b[TN];
#pragma unroll
            for (int i = 0; i < TM; i++) a[i] = As[k][ty * TM + i];
#pragma unroll
            for (int j = 0; j < TN; j++) b[j] = Bs[k][tx * TN + j];
#pragma unroll
            for (int i = 0; i < TM; i++)
#pragma unroll
                for (int j = 0; j < TN; j++) acc[i][j] += a[i] * b[j];
        }
        __syncthreads();
    }
#pragma unroll
    for (int i = 0; i < TM; i++) {
        int row = rowBase + ty * TM + i;
        if (row >= nrows) continue;
#pragma unroll
        for (int j = 0; j < TN; j++) {
            int col = colBase + tx * TN + j;
            C[(size_t)row * ldc + col] = fmaxf(acc[i][j] + bias[col], 0.0f);
        }
    }
}

__global__ void __launch_bounds__(256)
mlp2_kernel(const float* __restrict__ Wg2, const float* __restrict__ bias,
            float* __restrict__ out) {
    constexpr int BM = 8, BN = 128, KC = 16, TM = 1, TN = 4, NT = 256;
    __shared__ __align__(16) float As[KC][BM];
    __shared__ __align__(16) float Bs[KC][BN];
    const float* A = g_mlp1; const float* B = Wg2; float* C = out;
    const int lda = 1024, ldb = 128, ldc = 128, nrows = N_GRAPHS, K = 1024;
    int tid = threadIdx.x;
    int tx = tid % (BN / TN), ty = tid / (BN / TN);
    int rowBase = blockIdx.y * BM, colBase = blockIdx.x * BN;
    float acc[TM][TN];
#pragma unroll
    for (int i = 0; i < TM; i++)
#pragma unroll
        for (int j = 0; j < TN; j++) acc[i][j] = 0.0f;
    for (int kc = 0; kc < K; kc += KC) {
        for (int e = tid; e < BM * KC; e += NT) {
            int r = e / KC, k = e % KC;
            int row = rowBase + r;
            As[k][r] = (row < nrows) ? A[(size_t)row * lda + kc + k] : 0.0f;
        }
#pragma unroll
        for (int e = tid * 4; e < KC * BN; e += NT * 4) {
            int k = e / BN, c = e % BN;
            *(float4*)&Bs[k][c] = *(const float4*)&B[(size_t)(kc + k) * ldb + colBase + c];
        }
        __syncthreads();
#pragma unroll
        for (int k = 0; k < KC; k++) {
            float a[TM], b[TN];
#pragma unroll
            for (int i = 0; i < TM; i++) a[i] = As[k][ty * TM + i];
#pragma unroll
            for (int j = 0; j < TN; j++) b[j] = Bs[k][tx * TN + j];
#pragma unroll
            for (int i = 0; i < TM; i++)
#pragma unroll
                for (int j = 0; j < TN; j++) acc[i][j] += a[i] * b[j];
        }
        __syncthreads();
    }
#pragma unroll
    for (int i = 0; i < TM; i++) {
        int row = rowBase + ty * TM + i;
        if (row >= nrows) continue;
#pragma unroll
        for (int j = 0; j < TN; j++) {
            int col = colBase + tx * TN + j;
            C[(size_t)row * ldc + col] = acc[i][j] + bias[col];
        }
    }
}

// ---------------- host ------------------------------------------------------
extern "C" void kernel_launch(void* const* d_in, const int* in_sizes, int n_in,
                              void* d_out, int out_size) {
    const float* x     = (const float*)d_in[0];
    const int*   ei    = (const int*)d_in[1];    // int32 (JAX x64 disabled)
    const int*   batch = (const int*)d_in[2];    // int32
    const float* W1    = (const float*)d_in[3];
    const float* b1    = (const float*)d_in[4];
    const float* W2    = (const float*)d_in[5];
    const float* b2    = (const float*)d_in[6];
    const float* Wg1   = (const float*)d_in[7];
    const float* bg1   = (const float*)d_in[8];
    const float* Wg2   = (const float*)d_in[9];
    const float* bg2   = (const float*)d_in[10];
    float*       out   = (float*)d_out;

    const int SMEM1 = 128 * 84 * 2 * 4;               // 86016 B
    const int SMEM2 = (128 * 132 + 256 * 36) * 4;     // 104448 B
    cudaFuncSetAttribute(gemm1_kernel, cudaFuncAttributeMaxDynamicSharedMemorySize, SMEM1);
    cudaFuncSetAttribute(gemm2_kernel, cudaFuncAttributeMaxDynamicSharedMemorySize, SMEM2);

    const int NB_SCAN = (N_NODES + 1023) / 1024;  // 98
    const int NB_ROWS = (N_NODES + 127) / 128;    // 782
    const int NB_AGG  = (N_NODES + 7) / 8;        // warp per node, 8 warps/CTA
    const int PREP_N  = 128 * 84 + 256 * 132 + N_GRAPHS * 256;

    // CSR build + prep
    zero_counts_kernel<<<(N_NODES + 255) / 256, 256>>>();
    hist_kernel<<<(N_EDGES + 255) / 256, 256>>>(ei);
    scan_chunks_kernel<<<NB_SCAN, 256>>>();
    scan_tops_kernel<<<1, 128>>>(NB_SCAN);
    scan_finalize_kernel<<<(N_NODES + 255) / 256, 256>>>();
    fill_kernel<<<(N_EDGES + 255) / 256, 256>>>(ei);
    prep_small_kernel<<<(PREP_N + 255) / 256, 256>>>(W1, W2);
    xh_kernel<<<(N_NODES * 40 + 255) / 256, 256>>>(x);

    // layer 1: high-occupancy aggregate, then tensor-core GEMM
    agg1_kernel<<<NB_AGG, 256>>>();
    gemm1_kernel<<<NB_ROWS, 512, SMEM1>>>(b1);

    // layer 2: aggregate, then GEMM + fused seg-max
    agg2_kernel<<<NB_AGG, 256>>>();
    gemm2_kernel<<<NB_ROWS, 512, SMEM2>>>(b2, batch);

    // MLP head
    mlp1_kernel<<<dim3(8, 8), 256>>>(Wg1, bg1);
    mlp2_kernel<<<dim3(1, 64), 256>>>(Wg2, bg2, out);
}

// round 12
// speedup vs baseline: 1.2831x; 1.1178x over previous
#include <cuda_runtime.h>
#include <cuda_fp16.h>
#include <cstdint>

#define N_NODES  100000
#define N_EDGES  1600000
#define N_GRAPHS 512

// ---------------- scratch (device globals) ----------------------------------
__device__ int      g_counts[N_NODES];
__device__ int      g_rowstart[N_NODES + 1];
__device__ int      g_pos[N_NODES];
__device__ int      g_esrc[N_EDGES];
__device__ int      g_blocksums[128];
__device__ float    g_dinv[N_NODES];
__device__ uint32_t g_W1h[128 * 44];    // W1^T [n][k2] fp16x2, 40 used + 4 pad
__device__ uint32_t g_W2h[256 * 64];    // W2^T [n][k2] fp16x2 (k=128 -> 64 half2)
__device__ __half2  g_xh[(size_t)N_NODES * 40];     // x fp16, 40 half2/row (78+2 pad)
__device__ __half2  g_aggXh[(size_t)N_NODES * 40];  // aggregated x, fp16
__device__ __half2  g_h1h[(size_t)N_NODES * 64];    // h1 fp16, 64 half2/row
__device__ __half2  g_aggHh[(size_t)N_NODES * 64];  // aggregated h1, fp16
__device__ float    g_pool[N_GRAPHS * 256];
__device__ float    g_mlp1[N_GRAPHS * 1024];

// ---------------- fp16 MMA helper -------------------------------------------
// D(f32) += A(f16) * B(f16): exact products, fp32 accumulate.
__device__ __forceinline__ void mma_f16(float* c, const uint32_t* a,
                                        uint32_t b0, uint32_t b1) {
    asm volatile(
        "mma.sync.aligned.m16n8k16.row.col.f32.f16.f16.f32 "
        "{%0,%1,%2,%3}, {%4,%5,%6,%7}, {%8,%9}, {%0,%1,%2,%3};"
        : "+f"(c[0]), "+f"(c[1]), "+f"(c[2]), "+f"(c[3])
        : "r"(a[0]), "r"(a[1]), "r"(a[2]), "r"(a[3]), "r"(b0), "r"(b1));
}

// ---------------- CSR build --------------------------------------------------
__global__ void hist_kernel(const int* __restrict__ ei) {
    int e = blockIdx.x * blockDim.x + threadIdx.x;
    if (e < N_EDGES) {
        int d = ei[N_EDGES + e];
        if (d >= 0 && d < N_NODES) atomicAdd(&g_counts[d], 1);
    }
}

__device__ __forceinline__ int warp_incl_scan(int x) {
    int lane = threadIdx.x & 31;
#pragma unroll
    for (int o = 1; o < 32; o <<= 1) {
        int y = __shfl_up_sync(0xffffffffu, x, o);
        if (lane >= o) x += y;
    }
    return x;
}

__global__ void scan_chunks_kernel() {
    int base = blockIdx.x * 1024;
    int t = threadIdx.x;
    int i0 = base + t * 4;
    int v[4];
#pragma unroll
    for (int j = 0; j < 4; j++) v[j] = (i0 + j < N_NODES) ? g_counts[i0 + j] : 0;
    int s = v[0] + v[1] + v[2] + v[3];
    int incl = warp_incl_scan(s);
    __shared__ int ws[8];
    int lane = t & 31, wid = t >> 5;
    if (lane == 31) ws[wid] = incl;
    __syncthreads();
    if (wid == 0) {
        int w = (lane < 8) ? ws[lane] : 0;
        w = warp_incl_scan(w);
        if (lane < 8) ws[lane] = w;
    }
    __syncthreads();
    int excl = incl - s + (wid ? ws[wid - 1] : 0);
    int run = excl;
#pragma unroll
    for (int j = 0; j < 4; j++) {
        if (i0 + j < N_NODES) g_rowstart[i0 + j] = run;
        run += v[j];
    }
    if (t == 255) g_blocksums[blockIdx.x] = excl + s;
}

__global__ void scan_tops_kernel(int nb) {
    int t = threadIdx.x;
    int v = (t < nb) ? g_blocksums[t] : 0;
    int incl = warp_incl_scan(v);
    __shared__ int ws[4];
    int lane = t & 31, wid = t >> 5;
    if (lane == 31) ws[wid] = incl;
    __syncthreads();
    if (wid == 0) {
        int w = (lane < 4) ? ws[lane] : 0;
        w = warp_incl_scan(w);
        if (lane < 4) ws[lane] = w;
    }
    __syncthreads();
    int tot_incl = incl + (wid ? ws[wid - 1] : 0);
    if (t < nb) g_blocksums[t] = tot_incl - v;
}

__global__ void scan_finalize_kernel() {
    int i = blockIdx.x * blockDim.x + threadIdx.x;
    if (i < N_NODES) {
        int v = g_rowstart[i] + g_blocksums[i >> 10];
        g_rowstart[i] = v;
        g_pos[i] = v;
        g_dinv[i] = rsqrtf((float)g_counts[i] + 1.0f);
    }
    if (i == 0) g_rowstart[N_NODES] = N_EDGES;
}

__global__ void fill_kernel(const int* __restrict__ ei) {
    int e = blockIdx.x * blockDim.x + threadIdx.x;
    if (e < N_EDGES) {
        int d = ei[N_EDGES + e];
        int s = ei[e];
        if (d >= 0 && d < N_NODES) {
            int idx = atomicAdd(&g_pos[d], 1);
            if (idx >= 0 && idx < N_EDGES) g_esrc[idx] = s;
        }
    }
}

// ---------------- prep_all: weights->fp16, zero counts/pool, x->fp16 --------
#define NW1   (128 * 44)
#define NW2   (256 * 64)
#define NPOOL (N_GRAPHS * 256)
#define NXH   (N_NODES * 40)
#define PREP_TOTAL (NW1 + NW2 + NPOOL + N_NODES + NXH)

__global__ void prep_all_kernel(const float* __restrict__ W1,
                                const float* __restrict__ W2,
                                const float* __restrict__ x) {
    int idx = blockIdx.x * blockDim.x + threadIdx.x;
    if (idx < NW1) {
        int n = idx / 44, k2 = idx % 44;
        int k = 2 * k2;
        float v0 = (k < 78) ? W1[k * 128 + n] : 0.0f;
        float v1 = (k + 1 < 78) ? W1[(k + 1) * 128 + n] : 0.0f;
        __half2 h = __floats2half2_rn(v0, v1);
        g_W1h[idx] = *(uint32_t*)&h;
    } else if (idx < NW1 + NW2) {
        int j = idx - NW1;
        int n = j / 64, k2 = j % 64;
        int k = 2 * k2;
        __half2 h = __floats2half2_rn(W2[k * 256 + n], W2[(k + 1) * 256 + n]);
        g_W2h[j] = *(uint32_t*)&h;
    } else if (idx < NW1 + NW2 + NPOOL) {
        g_pool[idx - NW1 - NW2] = 0.0f;
    } else if (idx < NW1 + NW2 + NPOOL + N_NODES) {
        g_counts[idx - NW1 - NW2 - NPOOL] = 0;
    } else if (idx < PREP_TOTAL) {
        int base = idx - NW1 - NW2 - NPOOL - N_NODES;
        int row = base / 40, q = base % 40;
        int c = q * 2;
        float v0 = (c < 78) ? x[(size_t)row * 78 + c] : 0.0f;
        float v1 = (c + 1 < 78) ? x[(size_t)row * 78 + c + 1] : 0.0f;
        g_xh[base] = __floats2half2_rn(v0, v1);
    }
}

// ---------------- agg1: aggregate xh -> aggXh (high occupancy, no smem) ------
__global__ void __launch_bounds__(256)
agg1_kernel() {
    int warp = (blockIdx.x * blockDim.x + threadIdx.x) >> 5;
    int lane = threadIdx.x & 31;
    if (warp >= N_NODES) return;
    int i = warp;
    float di = g_dinv[i];
    int beg = g_rowstart[i], end = g_rowstart[i + 1];
    float a0 = 0.f, a1 = 0.f, a2 = 0.f, a3 = 0.f;
    for (int e = beg; e < end; e++) {
        int s = g_esrc[e];
        float w = g_dinv[s] * di;
        const __half2* xs = g_xh + (size_t)s * 40;
        float2 p = __half22float2(xs[lane]);
        a0 += p.x * w; a1 += p.y * w;
        if (lane < 8) {
            float2 q = __half22float2(xs[32 + lane]);
            a2 += q.x * w; a3 += q.y * w;
        }
    }
    float sd = di * di;
    const __half2* xi = g_xh + (size_t)i * 40;
    float2 p = __half22float2(xi[lane]);
    a0 += p.x * sd; a1 += p.y * sd;
    if (lane < 8) {
        float2 q = __half22float2(xi[32 + lane]);
        a2 += q.x * sd; a3 += q.y * sd;
    }
    g_aggXh[(size_t)i * 40 + lane] = __floats2half2_rn(a0, a1);
    if (lane < 8)
        g_aggXh[(size_t)i * 40 + 32 + lane] = __floats2half2_rn(a2, a3);
}

// ---------------- agg2: aggregate h1h -> aggHh --------------------------------
__global__ void __launch_bounds__(256)
agg2_kernel() {
    int warp = (blockIdx.x * blockDim.x + threadIdx.x) >> 5;
    int lane = threadIdx.x & 31;
    if (warp >= N_NODES) return;
    int i = warp;
    float di = g_dinv[i];
    int beg = g_rowstart[i], end = g_rowstart[i + 1];
    float4 acc = make_float4(0.f, 0.f, 0.f, 0.f);
    for (int e = beg; e < end; e++) {
        int s = g_esrc[e];
        float w = g_dinv[s] * di;
        uint2 u = ((const uint2*)(g_h1h + (size_t)s * 64))[lane];
        float2 pa = __half22float2(*(__half2*)&u.x);
        float2 pb = __half22float2(*(__half2*)&u.y);
        acc.x += pa.x * w; acc.y += pa.y * w;
        acc.z += pb.x * w; acc.w += pb.y * w;
    }
    float sd = di * di;
    uint2 u = ((const uint2*)(g_h1h + (size_t)i * 64))[lane];
    float2 pa = __half22float2(*(__half2*)&u.x);
    float2 pb = __half22float2(*(__half2*)&u.y);
    acc.x += pa.x * sd; acc.y += pa.y * sd;
    acc.z += pb.x * sd; acc.w += pb.y * sd;
    __half2 h0 = __floats2half2_rn(acc.x, acc.y);
    __half2 h1 = __floats2half2_rn(acc.z, acc.w);
    uint2 o;
    o.x = *(uint32_t*)&h0;
    o.y = *(uint32_t*)&h1;
    ((uint2*)(g_aggHh + (size_t)i * 64))[lane] = o;
}

// ---------------- gemm1: aggXh @ W1 -> h1h (fp16 MMA, bias+relu) -------------
// block = 128 rows, 512 threads, 2 CTAs/SM. SMEM: As[128][44] + Bs[128][44] u32
// (u32 = half2, k-pair). Strides 44 (≡12 mod 32) -> conflict-free fragments.
__global__ void __launch_bounds__(512, 2)
gemm1_kernel(const float* __restrict__ bias) {
    extern __shared__ uint32_t sm1[];
    uint32_t* As = sm1;                 // 128*44
    uint32_t* Bs = sm1 + 128 * 44;      // 128*44
    int tid = threadIdx.x, wid = tid >> 5, lane = tid & 31;
    int tileBase = blockIdx.x * 128;

    // stage W1h -> Bs (11 uint4 per 44-u32 row)
    for (int idx = tid; idx < 128 * 11; idx += 512) {
        int n = idx / 11, q = idx % 11;
        ((uint4*)(Bs + n * 44))[q] = ((const uint4*)(g_W1h + n * 44))[q];
    }
    // stage aggXh -> As (fp16 passthrough; q=10 covers the 4-u32 pad with zeros)
    for (int idx = tid; idx < 128 * 11; idx += 512) {
        int row = idx / 11, q = idx % 11;
        int gi = tileBase + row;
        uint4 v = make_uint4(0u, 0u, 0u, 0u);
        if (q < 10 && gi < N_NODES)
            v = ((const uint4*)(g_aggXh + (size_t)gi * 40))[q];
        ((uint4*)(As + row * 44))[q] = v;
    }
    __syncthreads();

    // MMA: 16 warps, warp tile 32 rows x 32 cols, K=80 -> 5 k16-steps
    int lq = lane >> 2, lr = lane & 3;
    int warpRow = wid & 3, warpCol = wid >> 2;
    float c[2][4][4] = {};
#pragma unroll
    for (int ks = 0; ks < 5; ks++) {
        int k2 = ks * 8;
        uint32_t a[2][4];
#pragma unroll
        for (int am = 0; am < 2; am++) {
            int rr = warpRow * 32 + am * 16 + lq;
            a[am][0] = As[rr * 44 + k2 + lr];
            a[am][1] = As[(rr + 8) * 44 + k2 + lr];
            a[am][2] = As[rr * 44 + k2 + 4 + lr];
            a[am][3] = As[(rr + 8) * 44 + k2 + 4 + lr];
        }
#pragma unroll
        for (int an = 0; an < 4; an++) {
            int n = warpCol * 32 + an * 8 + lq;
            uint32_t b0 = Bs[n * 44 + k2 + lr];
            uint32_t b1 = Bs[n * 44 + k2 + 4 + lr];
            mma_f16(c[0][an], a[0], b0, b1);
            mma_f16(c[1][an], a[1], b0, b1);
        }
    }

    // epilogue -> h1h (bias + relu, fp16 pair stores)
#pragma unroll
    for (int am = 0; am < 2; am++) {
        int r0 = tileBase + warpRow * 32 + am * 16 + lq;
#pragma unroll
        for (int an = 0; an < 4; an++) {
            int col = warpCol * 32 + an * 8 + lr * 2;
            float bx = bias[col], by = bias[col + 1];
            float v0 = fmaxf(c[am][an][0] + bx, 0.f);
            float v1 = fmaxf(c[am][an][1] + by, 0.f);
            float v2 = fmaxf(c[am][an][2] + bx, 0.f);
            float v3 = fmaxf(c[am][an][3] + by, 0.f);
            if (r0 < N_NODES)
                g_h1h[(size_t)r0 * 64 + (col >> 1)] = __floats2half2_rn(v0, v1);
            if (r0 + 8 < N_NODES)
                g_h1h[(size_t)(r0 + 8) * 64 + (col >> 1)] = __floats2half2_rn(v2, v3);
        }
    }
}

// ---------------- gemm2: aggHh @ W2 -> relu -> seg-max into pool -------------
// block = 128 rows, 512 threads. SMEM: As[128][76] + Bs[256][20] u32 (half2).
// Strides 76 (≡12) / 20 (≡20) -> conflict-free fragments.
__global__ void __launch_bounds__(512)
gemm2_kernel(const float* __restrict__ bias, const int* __restrict__ batch) {
    extern __shared__ uint32_t sm2[];
    uint32_t* As = sm2;                  // 128*76
    uint32_t* Bs = sm2 + 128 * 76;       // 256*20
    int tid = threadIdx.x, wid = tid >> 5, lane = tid & 31;
    int tileBase = blockIdx.x * 128;

    // stage aggHh -> As: 64 u32 data (16 uint4) + 12 u32 pad (3 uint4) per row
    for (int idx = tid; idx < 128 * 19; idx += 512) {
        int row = idx / 19, q = idx % 19;
        int gi = tileBase + row;
        uint4 v = make_uint4(0u, 0u, 0u, 0u);
        if (q < 16 && gi < N_NODES)
            v = ((const uint4*)(g_aggHh + (size_t)gi * 64))[q];
        ((uint4*)(As + row * 76))[q] = v;
    }
    __syncthreads();

    // MMA: 16 warps, warp tile 32 rows x 64 cols; K chunked by 32 (16 u32)
    int lq = lane >> 2, lr = lane & 3;
    int warpRow = wid & 3, warpCol = wid >> 2;
    float c[2][8][4] = {};
    for (int ch = 0; ch < 4; ch++) {
        int kc2 = ch * 16;
        // stage W2h chunk -> Bs (4 uint4 per 20-u32 row; pad u32 16-19 unused)
        for (int idx = tid; idx < 256 * 4; idx += 512) {
            int n = idx / 4, q = idx % 4;
            ((uint4*)(Bs + n * 20))[q] = ((const uint4*)(g_W2h + n * 64 + kc2))[q];
        }
        __syncthreads();
#pragma unroll
        for (int ks = 0; ks < 2; ks++) {
            int k2l = ks * 8;
            uint32_t a[2][4];
#pragma unroll
            for (int am = 0; am < 2; am++) {
                int rr = warpRow * 32 + am * 16 + lq;
                a[am][0] = As[rr * 76 + kc2 + k2l + lr];
                a[am][1] = As[(rr + 8) * 76 + kc2 + k2l + lr];
                a[am][2] = As[rr * 76 + kc2 + k2l + 4 + lr];
                a[am][3] = As[(rr + 8) * 76 + kc2 + k2l + 4 + lr];
            }
#pragma unroll
            for (int an = 0; an < 8; an++) {
                int n = warpCol * 64 + an * 8 + lq;
                uint32_t b0 = Bs[n * 20 + k2l + lr];
                uint32_t b1 = Bs[n * 20 + k2l + 4 + lr];
                mma_f16(c[0][an], a[0], b0, b1);
                mma_f16(c[1][an], a[1], b0, b1);
            }
        }
        __syncthreads();
    }

    // epilogue: bias + relu, segment max straight into pool (h2 never stored)
#pragma unroll
    for (int am = 0; am < 2; am++) {
        int r0 = tileBase + warpRow * 32 + am * 16 + lq;
        int r1 = r0 + 8;
        int b_lo = (r0 < N_NODES) ? batch[r0] : -1;
        int b_hi = (r1 < N_NODES) ? batch[r1] : -1;
        if (b_lo >= N_GRAPHS) b_lo = -1;
        if (b_hi >= N_GRAPHS) b_hi = -1;
#pragma unroll
        for (int an = 0; an < 8; an++) {
            int col = warpCol * 64 + an * 8 + lr * 2;
            float bx = bias[col], by = bias[col + 1];
            float v0 = fmaxf(c[am][an][0] + bx, 0.f);
            float v1 = fmaxf(c[am][an][1] + by, 0.f);
            float v2 = fmaxf(c[am][an][2] + bx, 0.f);
            float v3 = fmaxf(c[am][an][3] + by, 0.f);
            if (b_lo == b_hi && b_lo >= 0) {
                atomicMax((int*)&g_pool[(size_t)b_lo * 256 + col],
                          __float_as_int(fmaxf(v0, v2)));
                atomicMax((int*)&g_pool[(size_t)b_lo * 256 + col + 1],
                          __float_as_int(fmaxf(v1, v3)));
            } else {
                if (b_lo >= 0) {
                    atomicMax((int*)&g_pool[(size_t)b_lo * 256 + col], __float_as_int(v0));
                    atomicMax((int*)&g_pool[(size_t)b_lo * 256 + col + 1], __float_as_int(v1));
                }
                if (b_hi >= 0) {
                    atomicMax((int*)&g_pool[(size_t)b_hi * 256 + col], __float_as_int(v2));
                    atomicMax((int*)&g_pool[(size_t)b_hi * 256 + col + 1], __float_as_int(v3));
                }
            }
        }
    }
}

// ---------------- fp32 MLP head (small) -------------------------------------
__global__ void __launch_bounds__(256)
mlp1_kernel(const float* __restrict__ Wg1, const float* __restrict__ bias) {
    constexpr int BM = 64, BN = 128, KC = 16, TM = 8, TN = 4, NT = 256;
    __shared__ __align__(16) float As[KC][BM];
    __shared__ __align__(16) float Bs[KC][BN];
    const float* A = g_pool; const float* B = Wg1; float* C = g_mlp1;
    const int lda = 256, ldb = 1024, ldc = 1024, nrows = N_GRAPHS, K = 256;
    int tid = threadIdx.x;
    int tx = tid % (BN / TN), ty = tid / (BN / TN);
    int rowBase = blockIdx.y * BM, colBase = blockIdx.x * BN;
    float acc[TM][TN];
#pragma unroll
    for (int i = 0; i < TM; i++)
#pragma unroll
        for (int j = 0; j < TN; j++) acc[i][j] = 0.0f;
    for (int kc = 0; kc < K; kc += KC) {
#pragma unroll
        for (int e = tid * 4; e < BM * KC; e += NT * 4) {
            int r = e / KC, k = e % KC;
            int row = rowBase + r;
            float4 v = (row < nrows) ? *(const float4*)&A[(size_t)row * lda + kc + k]
                                     : make_float4(0.f, 0.f, 0.f, 0.f);
            As[k][r] = v.x; As[k + 1][r] = v.y; As[k + 2][r] = v.z; As[k + 3][r] = v.w;
        }
#pragma unroll
        for (int e = tid * 4; e < KC * BN; e += NT * 4) {
            int k = e / BN, c = e % BN;
            *(float4*)&Bs[k][c] = *(const float4*)&B[(size_t)(kc + k) * ldb + colBase + c];
        }
        __syncthreads();
#pragma unroll
        for (int k = 0; k < KC; k++) {
            float a[TM], b[TN];
#pragma unroll
            for (int i = 0; i < TM; i++) a[i] = As[k][ty * TM + i];
#pragma unroll
            for (int j = 0; j < TN; j++) b[j] = Bs[k][tx * TN + j];
#pragma unroll
            for (int i = 0; i < TM; i++)
#pragma unroll
                for (int j = 0; j < TN; j++) acc[i][j] += a[i] * b[j];
        }
        __syncthreads();
    }
#pragma unroll
    for (int i = 0; i < TM; i++) {
        int row = rowBase + ty * TM + i;
        if (row >= nrows) continue;
#pragma unroll
        for (int j = 0; j < TN; j++) {
            int col = colBase + tx * TN + j;
            C[(size_t)row * ldc + col] = fmaxf(acc[i][j] + bias[col], 0.0f);
        }
    }
}

__global__ void __launch_bounds__(256)
mlp2_kernel(const float* __restrict__ Wg2, const float* __restrict__ bias,
            float* __restrict__ out) {
    constexpr int BM = 8, BN = 128, KC = 16, TM = 1, TN = 4, NT = 256;
    __shared__ __align__(16) float As[KC][BM];
    __shared__ __align__(16) float Bs[KC][BN];
    const float* A = g_mlp1; const float* B = Wg2; float* C = out;
    const int lda = 1024, ldb = 128, ldc = 128, nrows = N_GRAPHS, K = 1024;
    int tid = threadIdx.x;
    int tx = tid % (BN / TN), ty = tid / (BN / TN);
    int rowBase = blockIdx.y * BM, colBase = blockIdx.x * BN;
    float acc[TM][TN];
#pragma unroll
    for (int i = 0; i < TM; i++)
#pragma unroll
        for (int j = 0; j < TN; j++) acc[i][j] = 0.0f;
    for (int kc = 0; kc < K; kc += KC) {
        for (int e = tid; e < BM * KC; e += NT) {
            int r = e / KC, k = e % KC;
            int row = rowBase + r;
            As[k][r] = (row < nrows) ? A[(size_t)row * lda + kc + k] : 0.0f;
        }
#pragma unroll
        for (int e = tid * 4; e < KC * BN; e += NT * 4) {
            int k = e / BN, c = e % BN;
            *(float4*)&Bs[k][c] = *(const float4*)&B[(size_t)(kc + k) * ldb + colBase + c];
        }
        __syncthreads();
#pragma unroll
        for (int k = 0; k < KC; k++) {
            float a[TM], b[TN];
#pragma unroll
            for (int i = 0; i < TM; i++) a[i] = As[k][ty * TM + i];
#pragma unroll
            for (int j = 0; j < TN; j++) b[j] = Bs[k][tx * TN + j];
#pragma unroll
            for (int i = 0; i < TM; i++)
#pragma unroll
                for (int j = 0; j < TN; j++) acc[i][j] += a[i] * b[j];
        }
        __syncthreads();
    }
#pragma unroll
    for (int i = 0; i < TM; i++) {
        int row = rowBase + ty * TM + i;
        if (row >= nrows) continue;
#pragma unroll
        for (int j = 0; j < TN; j++) {
            int col = colBase + tx * TN + j;
            C[(size_t)row * ldc + col] = acc[i][j] + bias[col];
        }
    }
}

// ---------------- host ------------------------------------------------------
extern "C" void kernel_launch(void* const* d_in, const int* in_sizes, int n_in,
                              void* d_out, int out_size) {
    const float* x     = (const float*)d_in[0];
    const int*   ei    = (const int*)d_in[1];    // int32 (JAX x64 disabled)
    const int*   batch = (const int*)d_in[2];    // int32
    const float* W1    = (const float*)d_in[3];
    const float* b1    = (const float*)d_in[4];
    const float* W2    = (const float*)d_in[5];
    const float* b2    = (const float*)d_in[6];
    const float* Wg1   = (const float*)d_in[7];
    const float* bg1   = (const float*)d_in[8];
    const float* Wg2   = (const float*)d_in[9];
    const float* bg2   = (const float*)d_in[10];
    float*       out   = (float*)d_out;

    const int SMEM1 = 128 * 44 * 2 * 4;               // 45056 B
    const int SMEM2 = (128 * 76 + 256 * 20) * 4;      // 59392 B
    cudaFuncSetAttribute(gemm1_kernel, cudaFuncAttributeMaxDynamicSharedMemorySize, SMEM1);
    cudaFuncSetAttribute(gemm2_kernel, cudaFuncAttributeMaxDynamicSharedMemorySize, SMEM2);

    const int NB_SCAN = (N_NODES + 1023) / 1024;  // 98
    const int NB_ROWS = (N_NODES + 127) / 128;    // 782
    const int NB_AGG  = (N_NODES + 7) / 8;        // warp per node, 8 warps/CTA

    // prep (weights fp16, zero counts/pool, x fp16) + CSR build
    prep_all_kernel<<<(PREP_TOTAL + 255) / 256, 256>>>(W1, W2, x);
    hist_kernel<<<(N_EDGES + 255) / 256, 256>>>(ei);
    scan_chunks_kernel<<<NB_SCAN, 256>>>();
    scan_tops_kernel<<<1, 128>>>(NB_SCAN);
    scan_finalize_kernel<<<(N_NODES + 255) / 256, 256>>>();
    fill_kernel<<<(N_EDGES + 255) / 256, 256>>>(ei);

    // layer 1: high-occupancy aggregate, then fp16 tensor-core GEMM
    agg1_kernel<<<NB_AGG, 256>>>();
    gemm1_kernel<<<NB_ROWS, 512, SMEM1>>>(b1);

    // layer 2: aggregate, then GEMM + fused seg-max
    agg2_kernel<<<NB_AGG, 256>>>();
    gemm2_kernel<<<NB_ROWS, 512, SMEM2>>>(b2, batch);

    // MLP head
    mlp1_kernel<<<dim3(8, 8), 256>>>(Wg1, bg1);
    mlp2_kernel<<<dim3(1, 64), 256>>>(Wg2, bg2, out);
}

// round 13
// speedup vs baseline: 1.5196x; 1.1842x over previous
#include <cuda_runtime.h>
#include <cuda_fp16.h>
#include <cstdint>

#define N_NODES  100000
#define N_EDGES  1600000
#define N_GRAPHS 512

// ---------------- scratch (device globals) ----------------------------------
__device__ int      g_counts[N_NODES];
__device__ int      g_rowstart[N_NODES + 1];
__device__ int      g_pos[N_NODES];
__device__ int      g_esrc[N_EDGES];
__device__ int      g_blocksums[128];
__device__ float    g_dinv[N_NODES];
__device__ uint32_t g_W1h[128 * 44];    // W1^T [n][k2] fp16x2, 40 used + 4 pad
__device__ uint32_t g_W2h[256 * 64];    // W2^T [n][k2] fp16x2 (k=128 -> 64 half2)
__device__ __half2  g_xh[(size_t)N_NODES * 40];     // x*dinv fp16, 40 half2/row
__device__ __half2  g_aggXh[(size_t)N_NODES * 40];  // aggregated x, fp16
__device__ __half2  g_h1h[(size_t)N_NODES * 64];    // h1*dinv fp16, 64 half2/row
__device__ __half2  g_aggHh[(size_t)N_NODES * 64];  // aggregated h1, fp16
__device__ float    g_pool[N_GRAPHS * 256];
__device__ float    g_mlp1[N_GRAPHS * 1024];

// ---------------- fp16 MMA helper -------------------------------------------
__device__ __forceinline__ void mma_f16(float* c, const uint32_t* a,
                                        uint32_t b0, uint32_t b1) {
    asm volatile(
        "mma.sync.aligned.m16n8k16.row.col.f32.f16.f16.f32 "
        "{%0,%1,%2,%3}, {%4,%5,%6,%7}, {%8,%9}, {%0,%1,%2,%3};"
        : "+f"(c[0]), "+f"(c[1]), "+f"(c[2]), "+f"(c[3])
        : "r"(a[0]), "r"(a[1]), "r"(a[2]), "r"(a[3]), "r"(b0), "r"(b1));
}

// ---------------- CSR build --------------------------------------------------
__global__ void hist_kernel(const int* __restrict__ ei) {
    int e = blockIdx.x * blockDim.x + threadIdx.x;
    if (e < N_EDGES) {
        int d = ei[N_EDGES + e];
        if (d >= 0 && d < N_NODES) atomicAdd(&g_counts[d], 1);
    }
}

__device__ __forceinline__ int warp_incl_scan(int x) {
    int lane = threadIdx.x & 31;
#pragma unroll
    for (int o = 1; o < 32; o <<= 1) {
        int y = __shfl_up_sync(0xffffffffu, x, o);
        if (lane >= o) x += y;
    }
    return x;
}

__global__ void scan_chunks_kernel() {
    int base = blockIdx.x * 1024;
    int t = threadIdx.x;
    int i0 = base + t * 4;
    int v[4];
#pragma unroll
    for (int j = 0; j < 4; j++) v[j] = (i0 + j < N_NODES) ? g_counts[i0 + j] : 0;
    int s = v[0] + v[1] + v[2] + v[3];
    int incl = warp_incl_scan(s);
    __shared__ int ws[8];
    int lane = t & 31, wid = t >> 5;
    if (lane == 31) ws[wid] = incl;
    __syncthreads();
    if (wid == 0) {
        int w = (lane < 8) ? ws[lane] : 0;
        w = warp_incl_scan(w);
        if (lane < 8) ws[lane] = w;
    }
    __syncthreads();
    int excl = incl - s + (wid ? ws[wid - 1] : 0);
    int run = excl;
#pragma unroll
    for (int j = 0; j < 4; j++) {
        if (i0 + j < N_NODES) g_rowstart[i0 + j] = run;
        run += v[j];
    }
    if (t == 255) g_blocksums[blockIdx.x] = excl + s;
}

__global__ void scan_tops_kernel(int nb) {
    int t = threadIdx.x;
    int v = (t < nb) ? g_blocksums[t] : 0;
    int incl = warp_incl_scan(v);
    __shared__ int ws[4];
    int lane = t & 31, wid = t >> 5;
    if (lane == 31) ws[wid] = incl;
    __syncthreads();
    if (wid == 0) {
        int w = (lane < 4) ? ws[lane] : 0;
        w = warp_incl_scan(w);
        if (lane < 4) ws[lane] = w;
    }
    __syncthreads();
    int tot_incl = incl + (wid ? ws[wid - 1] : 0);
    if (t < nb) g_blocksums[t] = tot_incl - v;
}

__global__ void scan_finalize_kernel() {
    int i = blockIdx.x * blockDim.x + threadIdx.x;
    if (i < N_NODES) {
        int v = g_rowstart[i] + g_blocksums[i >> 10];
        g_rowstart[i] = v;
        g_pos[i] = v;
        g_dinv[i] = rsqrtf((float)g_counts[i] + 1.0f);
    }
    if (i == 0) g_rowstart[N_NODES] = N_EDGES;
}

// fill CSR + build pre-scaled xh = x*dinv (both need scan_finalize)
#define FILL_TOTAL (N_EDGES + N_NODES * 40)
__global__ void fill_xh_kernel(const int* __restrict__ ei,
                               const float* __restrict__ x) {
    int idx = blockIdx.x * blockDim.x + threadIdx.x;
    if (idx < N_EDGES) {
        int d = ei[N_EDGES + idx];
        int s = ei[idx];
        if (d >= 0 && d < N_NODES) {
            int p = atomicAdd(&g_pos[d], 1);
            if (p >= 0 && p < N_EDGES) g_esrc[p] = s;
        }
    } else if (idx < FILL_TOTAL) {
        int base = idx - N_EDGES;
        int row = base / 40, q = base % 40;
        int c = q * 2;
        float di = g_dinv[row];
        float v0 = (c < 78) ? x[(size_t)row * 78 + c] * di : 0.0f;
        float v1 = (c + 1 < 78) ? x[(size_t)row * 78 + c + 1] * di : 0.0f;
        g_xh[base] = __floats2half2_rn(v0, v1);
    }
}

// ---------------- prep_all: weights->fp16, zero counts/pool ------------------
#define NW1   (128 * 44)
#define NW2   (256 * 64)
#define NPOOL (N_GRAPHS * 256)
#define PREP_TOTAL (NW1 + NW2 + NPOOL + N_NODES)

__global__ void prep_all_kernel(const float* __restrict__ W1,
                                const float* __restrict__ W2) {
    int idx = blockIdx.x * blockDim.x + threadIdx.x;
    if (idx < NW1) {
        int n = idx / 44, k2 = idx % 44;
        int k = 2 * k2;
        float v0 = (k < 78) ? W1[k * 128 + n] : 0.0f;
        float v1 = (k + 1 < 78) ? W1[(k + 1) * 128 + n] : 0.0f;
        __half2 h = __floats2half2_rn(v0, v1);
        g_W1h[idx] = *(uint32_t*)&h;
    } else if (idx < NW1 + NW2) {
        int j = idx - NW1;
        int n = j / 64, k2 = j % 64;
        int k = 2 * k2;
        __half2 h = __floats2half2_rn(W2[k * 256 + n], W2[(k + 1) * 256 + n]);
        g_W2h[j] = *(uint32_t*)&h;
    } else if (idx < NW1 + NW2 + NPOOL) {
        g_pool[idx - NW1 - NW2] = 0.0f;
    } else if (idx < PREP_TOTAL) {
        g_counts[idx - NW1 - NW2 - NPOOL] = 0;
    }
}

// ---------------- agg1: sum pre-scaled xh -> aggXh = di*(sum + self) ---------
__global__ void __launch_bounds__(256)
agg1_kernel() {
    int warp = (blockIdx.x * blockDim.x + threadIdx.x) >> 5;
    int lane = threadIdx.x & 31;
    if (warp >= N_NODES) return;
    int i = warp;
    float di = g_dinv[i];
    int beg = g_rowstart[i], end = g_rowstart[i + 1];
    float a0 = 0.f, a1 = 0.f, a2 = 0.f, a3 = 0.f;
    for (int e = beg; e < end; e++) {
        int s = g_esrc[e];
        const __half2* xs = g_xh + (size_t)s * 40;
        float2 p = __half22float2(xs[lane]);
        a0 += p.x; a1 += p.y;
        if (lane < 8) {
            float2 q = __half22float2(xs[32 + lane]);
            a2 += q.x; a3 += q.y;
        }
    }
    const __half2* xi = g_xh + (size_t)i * 40;
    float2 p = __half22float2(xi[lane]);
    a0 += p.x; a1 += p.y;
    if (lane < 8) {
        float2 q = __half22float2(xi[32 + lane]);
        a2 += q.x; a3 += q.y;
    }
    g_aggXh[(size_t)i * 40 + lane] = __floats2half2_rn(a0 * di, a1 * di);
    if (lane < 8)
        g_aggXh[(size_t)i * 40 + 32 + lane] = __floats2half2_rn(a2 * di, a3 * di);
}

// ---------------- agg2: sum pre-scaled h1h -> aggHh = di*(sum + self) --------
__global__ void __launch_bounds__(256)
agg2_kernel() {
    int warp = (blockIdx.x * blockDim.x + threadIdx.x) >> 5;
    int lane = threadIdx.x & 31;
    if (warp >= N_NODES) return;
    int i = warp;
    float di = g_dinv[i];
    int beg = g_rowstart[i], end = g_rowstart[i + 1];
    float4 acc = make_float4(0.f, 0.f, 0.f, 0.f);
    for (int e = beg; e < end; e++) {
        int s = g_esrc[e];
        uint2 u = ((const uint2*)(g_h1h + (size_t)s * 64))[lane];
        float2 pa = __half22float2(*(__half2*)&u.x);
        float2 pb = __half22float2(*(__half2*)&u.y);
        acc.x += pa.x; acc.y += pa.y;
        acc.z += pb.x; acc.w += pb.y;
    }
    uint2 u = ((const uint2*)(g_h1h + (size_t)i * 64))[lane];
    float2 pa = __half22float2(*(__half2*)&u.x);
    float2 pb = __half22float2(*(__half2*)&u.y);
    acc.x += pa.x; acc.y += pa.y;
    acc.z += pb.x; acc.w += pb.y;
    __half2 h0 = __floats2half2_rn(acc.x * di, acc.y * di);
    __half2 h1 = __floats2half2_rn(acc.z * di, acc.w * di);
    uint2 o;
    o.x = *(uint32_t*)&h0;
    o.y = *(uint32_t*)&h1;
    ((uint2*)(g_aggHh + (size_t)i * 64))[lane] = o;
}

// ---------------- gemm1: aggXh @ W1 -> h1h = relu(..)*dinv (fp16 MMA) --------
__global__ void __launch_bounds__(512, 2)
gemm1_kernel(const float* __restrict__ bias) {
    extern __shared__ uint32_t sm1[];
    uint32_t* As = sm1;                 // 128*44
    uint32_t* Bs = sm1 + 128 * 44;      // 128*44
    int tid = threadIdx.x, wid = tid >> 5, lane = tid & 31;
    int tileBase = blockIdx.x * 128;

    for (int idx = tid; idx < 128 * 11; idx += 512) {
        int n = idx / 11, q = idx % 11;
        ((uint4*)(Bs + n * 44))[q] = ((const uint4*)(g_W1h + n * 44))[q];
    }
    for (int idx = tid; idx < 128 * 11; idx += 512) {
        int row = idx / 11, q = idx % 11;
        int gi = tileBase + row;
        uint4 v = make_uint4(0u, 0u, 0u, 0u);
        if (q < 10 && gi < N_NODES)
            v = ((const uint4*)(g_aggXh + (size_t)gi * 40))[q];
        ((uint4*)(As + row * 44))[q] = v;
    }
    __syncthreads();

    int lq = lane >> 2, lr = lane & 3;
    int warpRow = wid & 3, warpCol = wid >> 2;
    float c[2][4][4] = {};
#pragma unroll
    for (int ks = 0; ks < 5; ks++) {
        int k2 = ks * 8;
        uint32_t a[2][4];
#pragma unroll
        for (int am = 0; am < 2; am++) {
            int rr = warpRow * 32 + am * 16 + lq;
            a[am][0] = As[rr * 44 + k2 + lr];
            a[am][1] = As[(rr + 8) * 44 + k2 + lr];
            a[am][2] = As[rr * 44 + k2 + 4 + lr];
            a[am][3] = As[(rr + 8) * 44 + k2 + 4 + lr];
        }
#pragma unroll
        for (int an = 0; an < 4; an++) {
            int n = warpCol * 32 + an * 8 + lq;
            uint32_t b0 = Bs[n * 44 + k2 + lr];
            uint32_t b1 = Bs[n * 44 + k2 + 4 + lr];
            mma_f16(c[0][an], a[0], b0, b1);
            mma_f16(c[1][an], a[1], b0, b1);
        }
    }

    // epilogue -> h1h = relu(v+b) * dinv[row]  (pre-scaled for agg2)
#pragma unroll
    for (int am = 0; am < 2; am++) {
        int r0 = tileBase + warpRow * 32 + am * 16 + lq;
        float d0 = (r0 < N_NODES) ? g_dinv[r0] : 0.f;
        float d1 = (r0 + 8 < N_NODES) ? g_dinv[r0 + 8] : 0.f;
#pragma unroll
        for (int an = 0; an < 4; an++) {
            int col = warpCol * 32 + an * 8 + lr * 2;
            float bx = bias[col], by = bias[col + 1];
            float v0 = fmaxf(c[am][an][0] + bx, 0.f) * d0;
            float v1 = fmaxf(c[am][an][1] + by, 0.f) * d0;
            float v2 = fmaxf(c[am][an][2] + bx, 0.f) * d1;
            float v3 = fmaxf(c[am][an][3] + by, 0.f) * d1;
            if (r0 < N_NODES)
                g_h1h[(size_t)r0 * 64 + (col >> 1)] = __floats2half2_rn(v0, v1);
            if (r0 + 8 < N_NODES)
                g_h1h[(size_t)(r0 + 8) * 64 + (col >> 1)] = __floats2half2_rn(v2, v3);
        }
    }
}

// ---------------- gemm2: aggHh @ W2 -> relu -> warp-reduced seg-max ----------
__global__ void __launch_bounds__(512)
gemm2_kernel(const float* __restrict__ bias, const int* __restrict__ batch) {
    extern __shared__ uint32_t sm2[];
    uint32_t* As = sm2;                  // 128*76
    uint32_t* Bs = sm2 + 128 * 76;       // 256*20
    int tid = threadIdx.x, wid = tid >> 5, lane = tid & 31;
    int tileBase = blockIdx.x * 128;

    for (int idx = tid; idx < 128 * 19; idx += 512) {
        int row = idx / 19, q = idx % 19;
        int gi = tileBase + row;
        uint4 v = make_uint4(0u, 0u, 0u, 0u);
        if (q < 16 && gi < N_NODES)
            v = ((const uint4*)(g_aggHh + (size_t)gi * 64))[q];
        ((uint4*)(As + row * 76))[q] = v;
    }
    __syncthreads();

    int lq = lane >> 2, lr = lane & 3;
    int warpRow = wid & 3, warpCol = wid >> 2;
    float c[2][8][4] = {};
    for (int ch = 0; ch < 4; ch++) {
        int kc2 = ch * 16;
        for (int idx = tid; idx < 256 * 4; idx += 512) {
            int n = idx / 4, q = idx % 4;
            ((uint4*)(Bs + n * 20))[q] = ((const uint4*)(g_W2h + n * 64 + kc2))[q];
        }
        __syncthreads();
#pragma unroll
        for (int ks = 0; ks < 2; ks++) {
            int k2l = ks * 8;
            uint32_t a[2][4];
#pragma unroll
            for (int am = 0; am < 2; am++) {
                int rr = warpRow * 32 + am * 16 + lq;
                a[am][0] = As[rr * 76 + kc2 + k2l + lr];
                a[am][1] = As[(rr + 8) * 76 + kc2 + k2l + lr];
                a[am][2] = As[rr * 76 + kc2 + k2l + 4 + lr];
                a[am][3] = As[(rr + 8) * 76 + kc2 + k2l + 4 + lr];
            }
#pragma unroll
            for (int an = 0; an < 8; an++) {
                int n = warpCol * 64 + an * 8 + lq;
                uint32_t b0 = Bs[n * 20 + k2l + lr];
                uint32_t b1 = Bs[n * 20 + k2l + 4 + lr];
                mma_f16(c[0][an], a[0], b0, b1);
                mma_f16(c[1][an], a[1], b0, b1);
            }
        }
        __syncthreads();
    }

    // epilogue: warp holds 32 consecutive rows (warpRow block). If the whole
    // block is one graph (common: ~195 nodes/graph), reduce max across the
    // warp first -> 64 atomics/warp instead of 1024. Else exact per-row path.
    int blk = tileBase + warpRow * 32;
    bool fast = (blk + 31 < N_NODES) && (batch[blk] == batch[blk + 31]);
    if (fast) {
        int g = batch[blk];
        float* gp = g_pool + (size_t)g * 256;
#pragma unroll
        for (int an = 0; an < 8; an++) {
            int col = warpCol * 64 + an * 8 + lr * 2;
            float m0 = fmaxf(fmaxf(c[0][an][0], c[0][an][2]),
                             fmaxf(c[1][an][0], c[1][an][2]));
            float m1 = fmaxf(fmaxf(c[0][an][1], c[0][an][3]),
                             fmaxf(c[1][an][1], c[1][an][3]));
            m0 = fmaxf(m0 + bias[col], 0.f);
            m1 = fmaxf(m1 + bias[col + 1], 0.f);
#pragma unroll
            for (int o = 4; o < 32; o <<= 1) {
                m0 = fmaxf(m0, __shfl_xor_sync(0xffffffffu, m0, o));
                m1 = fmaxf(m1, __shfl_xor_sync(0xffffffffu, m1, o));
            }
            if (lane < 4) {
                atomicMax((int*)&gp[col], __float_as_int(m0));
                atomicMax((int*)&gp[col + 1], __float_as_int(m1));
            }
        }
    } else {
#pragma unroll
        for (int am = 0; am < 2; am++) {
            int r0 = blk + am * 16 + lq;
            int r1 = r0 + 8;
            int b_lo = (r0 < N_NODES) ? batch[r0] : -1;
            int b_hi = (r1 < N_NODES) ? batch[r1] : -1;
            if (b_lo >= N_GRAPHS) b_lo = -1;
            if (b_hi >= N_GRAPHS) b_hi = -1;
#pragma unroll
            for (int an = 0; an < 8; an++) {
                int col = warpCol * 64 + an * 8 + lr * 2;
                float bx = bias[col], by = bias[col + 1];
                float v0 = fmaxf(c[am][an][0] + bx, 0.f);
                float v1 = fmaxf(c[am][an][1] + by, 0.f);
                float v2 = fmaxf(c[am][an][2] + bx, 0.f);
                float v3 = fmaxf(c[am][an][3] + by, 0.f);
                if (b_lo == b_hi && b_lo >= 0) {
                    atomicMax((int*)&g_pool[(size_t)b_lo * 256 + col],
                              __float_as_int(fmaxf(v0, v2)));
                    atomicMax((int*)&g_pool[(size_t)b_lo * 256 + col + 1],
                              __float_as_int(fmaxf(v1, v3)));
                } else {
                    if (b_lo >= 0) {
                        atomicMax((int*)&g_pool[(size_t)b_lo * 256 + col],
                                  __float_as_int(v0));
                        atomicMax((int*)&g_pool[(size_t)b_lo * 256 + col + 1],
                                  __float_as_int(v1));
                    }
                    if (b_hi >= 0) {
                        atomicMax((int*)&g_pool[(size_t)b_hi * 256 + col],
                                  __float_as_int(v2));
                        atomicMax((int*)&g_pool[(size_t)b_hi * 256 + col + 1],
                                  __float_as_int(v3));
                    }
                }
            }
        }
    }
}

// ---------------- fp32 MLP head (small) -------------------------------------
__global__ void __launch_bounds__(256)
mlp1_kernel(const float* __restrict__ Wg1, const float* __restrict__ bias) {
    constexpr int BM = 64, BN = 128, KC = 16, TM = 8, TN = 4, NT = 256;
    __shared__ __align__(16) float As[KC][BM];
    __shared__ __align__(16) float Bs[KC][BN];
    const float* A = g_pool; const float* B = Wg1; float* C = g_mlp1;
    const int lda = 256, ldb = 1024, ldc = 1024, nrows = N_GRAPHS, K = 256;
    int tid = threadIdx.x;
    int tx = tid % (BN / TN), ty = tid / (BN / TN);
    int rowBase = blockIdx.y * BM, colBase = blockIdx.x * BN;
    float acc[TM][TN];
#pragma unroll
    for (int i = 0; i < TM; i++)
#pragma unroll
        for (int j = 0; j < TN; j++) acc[i][j] = 0.0f;
    for (int kc = 0; kc < K; kc += KC) {
#pragma unroll
        for (int e = tid * 4; e < BM * KC; e += NT * 4) {
            int r = e / KC, k = e % KC;
            int row = rowBase + r;
            float4 v = (row < nrows) ? *(const float4*)&A[(size_t)row * lda + kc + k]
                                     : make_float4(0.f, 0.f, 0.f, 0.f);
            As[k][r] = v.x; As[k + 1][r] = v.y; As[k + 2][r] = v.z; As[k + 3][r] = v.w;
        }
#pragma unroll
        for (int e = tid * 4; e < KC * BN; e += NT * 4) {
            int k = e / BN, c = e % BN;
            *(float4*)&Bs[k][c] = *(const float4*)&B[(size_t)(kc + k) * ldb + colBase + c];
        }
        __syncthreads();
#pragma unroll
        for (int k = 0; k < KC; k++) {
            float a[TM], b[TN];
#pragma unroll
            for (int i = 0; i < TM; i++) a[i] = As[k][ty * TM + i];
#pragma unroll
            for (int j = 0; j < TN; j++) b[j] = Bs[k][tx * TN + j];
#pragma unroll
            for (int i = 0; i < TM; i++)
#pragma unroll
                for (int j = 0; j < TN; j++) acc[i][j] += a[i] * b[j];
        }
        __syncthreads();
    }
#pragma unroll
    for (int i = 0; i < TM; i++) {
        int row = rowBase + ty * TM + i;
        if (row >= nrows) continue;
#pragma unroll
        for (int j = 0; j < TN; j++) {
            int col = colBase + tx * TN + j;
            C[(size_t)row * ldc + col] = fmaxf(acc[i][j] + bias[col], 0.0f);
        }
    }
}

__global__ void __launch_bounds__(256)
mlp2_kernel(const float* __restrict__ Wg2, const float* __restrict__ bias,
            float* __restrict__ out) {
    constexpr int BM = 8, BN = 128, KC = 16, TM = 1, TN = 4, NT = 256;
    __shared__ __align__(16) float As[KC][BM];
    __shared__ __align__(16) float Bs[KC][BN];
    const float* A = g_mlp1; const float* B = Wg2; float* C = out;
    const int lda = 1024, ldb = 128, ldc = 128, nrows = N_GRAPHS, K = 1024;
    int tid = threadIdx.x;
    int tx = tid % (BN / TN), ty = tid / (BN / TN);
    int rowBase = blockIdx.y * BM, colBase = blockIdx.x * BN;
    float acc[TM][TN];
#pragma unroll
    for (int i = 0; i < TM; i++)
#pragma unroll
        for (int j = 0; j < TN; j++) acc[i][j] = 0.0f;
    for (int kc = 0; kc < K; kc += KC) {
        for (int e = tid; e < BM * KC; e += NT) {
            int r = e / KC, k = e % KC;
            int row = rowBase + r;
            As[k][r] = (row < nrows) ? A[(size_t)row * lda + kc + k] : 0.0f;
        }
#pragma unroll
        for (int e = tid * 4; e < KC * BN; e += NT * 4) {
            int k = e / BN, c = e % BN;
            *(float4*)&Bs[k][c] = *(const float4*)&B[(size_t)(kc + k) * ldb + colBase + c];
        }
        __syncthreads();
#pragma unroll
        for (int k = 0; k < KC; k++) {
            float a[TM], b[TN];
#pragma unroll
            for (int i = 0; i < TM; i++) a[i] = As[k][ty * TM + i];
#pragma unroll
            for (int j = 0; j < TN; j++) b[j] = Bs[k][tx * TN + j];
#pragma unroll
            for (int i = 0; i < TM; i++)
#pragma unroll
                for (int j = 0; j < TN; j++) acc[i][j] += a[i] * b[j];
        }
        __syncthreads();
    }
#pragma unroll
    for (int i = 0; i < TM; i++) {
        int row = rowBase + ty * TM + i;
        if (row >= nrows) continue;
#pragma unroll
        for (int j = 0; j < TN; j++) {
            int col = colBase + tx * TN + j;
            C[(size_t)row * ldc + col] = acc[i][j] + bias[col];
        }
    }
}

// ---------------- host ------------------------------------------------------
extern "C" void kernel_launch(void* const* d_in, const int* in_sizes, int n_in,
                              void* d_out, int out_size) {
    const float* x     = (const float*)d_in[0];
    const int*   ei    = (const int*)d_in[1];    // int32 (JAX x64 disabled)
    const int*   batch = (const int*)d_in[2];    // int32
    const float* W1    = (const float*)d_in[3];
    const float* b1    = (const float*)d_in[4];
    const float* W2    = (const float*)d_in[5];
    const float* b2    = (const float*)d_in[6];
    const float* Wg1   = (const float*)d_in[7];
    const float* bg1   = (const float*)d_in[8];
    const float* Wg2   = (const float*)d_in[9];
    const float* bg2   = (const float*)d_in[10];
    float*       out   = (float*)d_out;

    const int SMEM1 = 128 * 44 * 2 * 4;               // 45056 B
    const int SMEM2 = (128 * 76 + 256 * 20) * 4;      // 59392 B
    cudaFuncSetAttribute(gemm1_kernel, cudaFuncAttributeMaxDynamicSharedMemorySize, SMEM1);
    cudaFuncSetAttribute(gemm2_kernel, cudaFuncAttributeMaxDynamicSharedMemorySize, SMEM2);

    const int NB_SCAN = (N_NODES + 1023) / 1024;  // 98
    const int NB_ROWS = (N_NODES + 127) / 128;    // 782
    const int NB_AGG  = (N_NODES + 7) / 8;        // warp per node, 8 warps/CTA

    // prep (weights fp16, zero counts/pool) + CSR build + scaled xh
    prep_all_kernel<<<(PREP_TOTAL + 255) / 256, 256>>>(W1, W2);
    hist_kernel<<<(N_EDGES + 255) / 256, 256>>>(ei);
    scan_chunks_kernel<<<NB_SCAN, 256>>>();
    scan_tops_kernel<<<1, 128>>>(NB_SCAN);
    scan_finalize_kernel<<<(N_NODES + 255) / 256, 256>>>();
    fill_xh_kernel<<<(FILL_TOTAL + 255) / 256, 256>>>(ei, x);

    // layer 1
    agg1_kernel<<<NB_AGG, 256>>>();
    gemm1_kernel<<<NB_ROWS, 512, SMEM1>>>(b1);

    // layer 2 (+ fused seg-max)
    agg2_kernel<<<NB_AGG, 256>>>();
    gemm2_kernel<<<NB_ROWS, 512, SMEM2>>>(b2, batch);

    // MLP head
    mlp1_kernel<<<dim3(8, 8), 256>>>(Wg1, bg1);
    mlp2_kernel<<<dim3(1, 64), 256>>>(Wg2, bg2, out);
}